// round 1
// baseline (speedup 1.0000x reference)
#include <cuda_runtime.h>
#include <math.h>

#define EMBED 1024
#define NQV   1024
#define NKV   2048
#define BATCH 4
#define NH    16
#define HD    64

// Scratch (allocation-free rule: __device__ globals)
__device__ float g_Q[BATCH * NQV * EMBED];   // 16 MB
__device__ float g_K[BATCH * NKV * EMBED];   // 32 MB
__device__ float g_V[BATCH * NKV * EMBED];   // 32 MB
__device__ float g_AO[BATCH * NQV * EMBED];  // 16 MB

// ---------------------------------------------------------------------------
// C[M,N] = A[M,K] @ B[N,K]^T + bias[N]
// Block tile 128x128, k-tile 8, 256 threads, 8x8 micro-tile per thread.
// ---------------------------------------------------------------------------
__global__ __launch_bounds__(256) void gemm_nt_bias(
    const float* __restrict__ A, const float* __restrict__ B,
    const float* __restrict__ bias, float* __restrict__ C,
    int M, int N, int K)
{
    __shared__ float As[8][132];   // As[k][m] (transposed store)
    __shared__ float Bs[8][132];   // Bs[k][n]

    const int bm = blockIdx.y * 128;
    const int bn = blockIdx.x * 128;
    const int tid = threadIdx.x;
    const int tx = tid & 15;       // 0..15 -> n micro index
    const int ty = tid >> 4;       // 0..15 -> m micro index
    const int lr = tid >> 1;       // 0..127 loader row
    const int lc = (tid & 1) * 4;  // 0 or 4 loader k-offset

    float acc[8][8];
#pragma unroll
    for (int i = 0; i < 8; i++)
#pragma unroll
        for (int j = 0; j < 8; j++) acc[i][j] = 0.f;

    const float* Ag = A + (size_t)(bm + lr) * K + lc;
    const float* Bg = B + (size_t)(bn + lr) * K + lc;

    for (int k0 = 0; k0 < K; k0 += 8) {
        float4 a = *(const float4*)(Ag + k0);
        float4 b = *(const float4*)(Bg + k0);
        As[lc + 0][lr] = a.x; As[lc + 1][lr] = a.y;
        As[lc + 2][lr] = a.z; As[lc + 3][lr] = a.w;
        Bs[lc + 0][lr] = b.x; Bs[lc + 1][lr] = b.y;
        Bs[lc + 2][lr] = b.z; Bs[lc + 3][lr] = b.w;
        __syncthreads();

#pragma unroll
        for (int kk = 0; kk < 8; kk++) {
            float4 a0 = *(const float4*)&As[kk][ty * 8];
            float4 a1 = *(const float4*)&As[kk][ty * 8 + 4];
            float4 b0 = *(const float4*)&Bs[kk][tx * 8];
            float4 b1 = *(const float4*)&Bs[kk][tx * 8 + 4];
            float av[8] = {a0.x, a0.y, a0.z, a0.w, a1.x, a1.y, a1.z, a1.w};
            float bv[8] = {b0.x, b0.y, b0.z, b0.w, b1.x, b1.y, b1.z, b1.w};
#pragma unroll
            for (int i = 0; i < 8; i++)
#pragma unroll
                for (int j = 0; j < 8; j++)
                    acc[i][j] = fmaf(av[i], bv[j], acc[i][j]);
        }
        __syncthreads();
    }

#pragma unroll
    for (int i = 0; i < 8; i++) {
        const int m = bm + ty * 8 + i;
        float* Cr = C + (size_t)m * N + bn + tx * 8;
#pragma unroll
        for (int j = 0; j < 8; j++)
            Cr[j] = acc[i][j] + bias[bn + tx * 8 + j];
    }
}

// ---------------------------------------------------------------------------
// Flash attention with key multiplicities: softmax(QK^T/sqrt(d) + log m) V
// One block per (q_tile 64, head, batch). 256 threads, 4x4 micro-tiles.
// ---------------------------------------------------------------------------
#define AST 68   // smem row stride (floats); 68*4B keeps 16B alignment

__global__ __launch_bounds__(256) void attn_kernel(
    const float* __restrict__ Q, const float* __restrict__ Kg_,
    const float* __restrict__ V, const float* __restrict__ mult,
    float* __restrict__ Oa)
{
    extern __shared__ float sm[];
    float* QsT = sm;                 // [64][AST]  QsT[d][q] (pre-scaled)
    float* KsT = QsT + 64 * AST;     // [64][AST]  KsT[d][k]
    float* Vs  = KsT + 64 * AST;     // [64][AST]  Vs[k][d]
    float* PsT = Vs  + 64 * AST;     // [64][AST]  PsT[k][q]
    float* lb  = PsT + 64 * AST;     // [64] log multiplicities

    const int qt = blockIdx.x, h = blockIdx.y, b = blockIdx.z;
    const int tid = threadIdx.x;
    const int tx = tid & 15;         // key micro col / out d col
    const int ty = tid >> 4;         // query micro row
    const int lr = tid >> 2;         // loader row 0..63
    const int lc = (tid & 3) * 16;   // loader d-offset 0,16,32,48

    // Load Q tile transposed, scale folded in
    {
        const float* Qg = Q + ((size_t)(b * NQV + qt * 64 + lr)) * EMBED + h * HD;
#pragma unroll
        for (int i = 0; i < 4; i++) {
            const int d = lc + i * 4;
            float4 v = *(const float4*)(Qg + d);
            QsT[(d + 0) * AST + lr] = v.x * 0.125f;
            QsT[(d + 1) * AST + lr] = v.y * 0.125f;
            QsT[(d + 2) * AST + lr] = v.z * 0.125f;
            QsT[(d + 3) * AST + lr] = v.w * 0.125f;
        }
    }

    float mrow[4], lrow[4], o[4][4];
#pragma unroll
    for (int i = 0; i < 4; i++) {
        mrow[i] = -1e30f; lrow[i] = 0.f;
#pragma unroll
        for (int j = 0; j < 4; j++) o[i][j] = 0.f;
    }

    for (int kt = 0; kt < NKV / 64; kt++) {
        // Load K (transposed) and V tiles
        const float* Kr = Kg_ + ((size_t)(b * NKV + kt * 64 + lr)) * EMBED + h * HD;
        const float* Vr = V   + ((size_t)(b * NKV + kt * 64 + lr)) * EMBED + h * HD;
#pragma unroll
        for (int i = 0; i < 4; i++) {
            const int d = lc + i * 4;
            float4 kv = *(const float4*)(Kr + d);
            KsT[(d + 0) * AST + lr] = kv.x;
            KsT[(d + 1) * AST + lr] = kv.y;
            KsT[(d + 2) * AST + lr] = kv.z;
            KsT[(d + 3) * AST + lr] = kv.w;
            float4 vv = *(const float4*)(Vr + d);
            *(float4*)&Vs[lr * AST + d] = vv;
        }
        if (tid < 64)
            lb[tid] = __logf(mult[(size_t)b * NKV + kt * 64 + tid]);
        __syncthreads();

        // S = Q K^T (scaled)
        float s[4][4];
#pragma unroll
        for (int i = 0; i < 4; i++)
#pragma unroll
            for (int j = 0; j < 4; j++) s[i][j] = 0.f;

#pragma unroll 8
        for (int d = 0; d < 64; d++) {
            float4 a  = *(const float4*)&QsT[d * AST + ty * 4];
            float4 bk = *(const float4*)&KsT[d * AST + tx * 4];
            float av[4] = {a.x, a.y, a.z, a.w};
            float bv[4] = {bk.x, bk.y, bk.z, bk.w};
#pragma unroll
            for (int i = 0; i < 4; i++)
#pragma unroll
                for (int j = 0; j < 4; j++)
                    s[i][j] = fmaf(av[i], bv[j], s[i][j]);
        }

        // logit bias: + log(multiplicity)
        float bj[4];
#pragma unroll
        for (int j = 0; j < 4; j++) bj[j] = lb[tx * 4 + j];
#pragma unroll
        for (int i = 0; i < 4; i++)
#pragma unroll
            for (int j = 0; j < 4; j++) s[i][j] += bj[j];

        // Online softmax per row (16 lanes share a row)
#pragma unroll
        for (int i = 0; i < 4; i++) {
            float rm = s[i][0];
#pragma unroll
            for (int j = 1; j < 4; j++) rm = fmaxf(rm, s[i][j]);
#pragma unroll
            for (int off = 1; off < 16; off <<= 1)
                rm = fmaxf(rm, __shfl_xor_sync(0xffffffffu, rm, off, 16));
            const float mn = fmaxf(mrow[i], rm);
            const float al = __expf(mrow[i] - mn);
            float rs = 0.f;
#pragma unroll
            for (int j = 0; j < 4; j++) {
                s[i][j] = __expf(s[i][j] - mn);
                rs += s[i][j];
            }
#pragma unroll
            for (int off = 1; off < 16; off <<= 1)
                rs += __shfl_xor_sync(0xffffffffu, rs, off, 16);
            lrow[i] = lrow[i] * al + rs;
            mrow[i] = mn;
#pragma unroll
            for (int j = 0; j < 4; j++) o[i][j] *= al;
        }

        // P -> smem (transposed: PsT[k][q])
#pragma unroll
        for (int i = 0; i < 4; i++)
#pragma unroll
            for (int j = 0; j < 4; j++)
                PsT[(tx * 4 + j) * AST + ty * 4 + i] = s[i][j];
        __syncthreads();

        // O += P V
#pragma unroll 8
        for (int k = 0; k < 64; k++) {
            float4 p  = *(const float4*)&PsT[k * AST + ty * 4];
            float4 vv = *(const float4*)&Vs[k * AST + tx * 4];
            float pv[4] = {p.x, p.y, p.z, p.w};
            float vvv[4] = {vv.x, vv.y, vv.z, vv.w};
#pragma unroll
            for (int i = 0; i < 4; i++)
#pragma unroll
                for (int j = 0; j < 4; j++)
                    o[i][j] = fmaf(pv[i], vvv[j], o[i][j]);
        }
        __syncthreads();
    }

    // Epilogue: normalize and write (b, q, h*64 + d)
#pragma unroll
    for (int i = 0; i < 4; i++) {
        const float inv = 1.f / lrow[i];
        float* Or = Oa + ((size_t)(b * NQV + qt * 64 + ty * 4 + i)) * EMBED
                       + h * HD + tx * 4;
#pragma unroll
        for (int j = 0; j < 4; j++)
            Or[j] = o[i][j] * inv;
    }
}

// ---------------------------------------------------------------------------
extern "C" void kernel_launch(void* const* d_in, const int* in_sizes, int n_in,
                              void* d_out, int out_size)
{
    const float* query = (const float*)d_in[0];
    const float* key   = (const float*)d_in[1];
    const float* value = (const float*)d_in[2];
    const float* mult  = (const float*)d_in[3];
    const float* wq_w  = (const float*)d_in[4];
    const float* wq_b  = (const float*)d_in[5];
    const float* wk_w  = (const float*)d_in[6];
    const float* wk_b  = (const float*)d_in[7];
    const float* wv_w  = (const float*)d_in[8];
    const float* wv_b  = (const float*)d_in[9];
    const float* wo_w  = (const float*)d_in[10];
    const float* wo_b  = (const float*)d_in[11];
    float* out = (float*)d_out;

    float *gq, *gk, *gv, *gao;
    cudaGetSymbolAddress((void**)&gq,  g_Q);
    cudaGetSymbolAddress((void**)&gk,  g_K);
    cudaGetSymbolAddress((void**)&gv,  g_V);
    cudaGetSymbolAddress((void**)&gao, g_AO);

    const int smem_attn = (4 * 64 * AST + 64) * (int)sizeof(float);  // 69888 B
    cudaFuncSetAttribute(attn_kernel,
                         cudaFuncAttributeMaxDynamicSharedMemorySize, smem_attn);

    // Projections
    dim3 gQ(EMBED / 128, (BATCH * NQV) / 128);   // (8, 32)
    dim3 gKV(EMBED / 128, (BATCH * NKV) / 128);  // (8, 64)
    gemm_nt_bias<<<gQ, 256>>>(query, wq_w, wq_b, gq, BATCH * NQV, EMBED, EMBED);
    gemm_nt_bias<<<gKV, 256>>>(key,   wk_w, wk_b, gk, BATCH * NKV, EMBED, EMBED);
    gemm_nt_bias<<<gKV, 256>>>(value, wv_w, wv_b, gv, BATCH * NKV, EMBED, EMBED);

    // Attention
    attn_kernel<<<dim3(NQV / 64, NH, BATCH), 256, smem_attn>>>(gq, gk, gv, mult, gao);

    // Output projection
    gemm_nt_bias<<<gQ, 256>>>(gao, wo_w, wo_b, out, BATCH * NQV, EMBED, EMBED);
}

// round 3
// speedup vs baseline: 1.4731x; 1.4731x over previous
#include <cuda_runtime.h>
#include <cuda_bf16.h>
#include <math.h>
#include <stdint.h>

#define EMBED 1024
#define NQV   1024
#define NKV   2048
#define BATCH 4
#define NH    16
#define HD    64

// ---------------------------------------------------------------------------
// Scratch (__device__ globals — allocation-free rule)
// ---------------------------------------------------------------------------
__device__ float g_Q[BATCH * NQV * EMBED];
__device__ float g_K[BATCH * NKV * EMBED];
__device__ float g_V[BATCH * NKV * EMBED];

__device__ __nv_bfloat16 g_qh[BATCH * NQV * EMBED], g_ql[BATCH * NQV * EMBED];
__device__ __nv_bfloat16 g_kh[BATCH * NKV * EMBED], g_kl[BATCH * NKV * EMBED];
__device__ __nv_bfloat16 g_vh[BATCH * NKV * EMBED], g_vl[BATCH * NKV * EMBED];
__device__ __nv_bfloat16 g_aoh[BATCH * NQV * EMBED], g_aol[BATCH * NQV * EMBED];
__device__ __nv_bfloat16 g_wqh[EMBED * EMBED], g_wql[EMBED * EMBED];
__device__ __nv_bfloat16 g_wkh[EMBED * EMBED], g_wkl[EMBED * EMBED];
__device__ __nv_bfloat16 g_wvh[EMBED * EMBED], g_wvl[EMBED * EMBED];
__device__ __nv_bfloat16 g_woh[EMBED * EMBED], g_wol[EMBED * EMBED];

// ---------------------------------------------------------------------------
// PTX helpers (sm_80-compatible ISA only — this toolchain targets compute_103
// without the 'a' feature set, so no tcgen05/TMEM)
// ---------------------------------------------------------------------------
__device__ __forceinline__ uint32_t smem_u32(const void* p) {
    uint32_t a;
    asm("{ .reg .u64 t; cvta.to.shared.u64 t, %1; cvt.u32.u64 %0, t; }"
        : "=r"(a) : "l"(p));
    return a;
}
__device__ __forceinline__ void cp16(uint32_t dst, const void* src) {
    asm volatile("cp.async.cg.shared.global [%0], [%1], 16;"
                 :: "r"(dst), "l"(src) : "memory");
}
#define CP_COMMIT() asm volatile("cp.async.commit_group;" ::: "memory")
#define CP_WAIT(n)  asm volatile("cp.async.wait_group %0;" :: "n"(n) : "memory")

__device__ __forceinline__ void ldsm4(uint32_t* r, uint32_t addr) {
    asm volatile("ldmatrix.sync.aligned.m8n8.x4.shared.b16 {%0,%1,%2,%3}, [%4];"
                 : "=r"(r[0]), "=r"(r[1]), "=r"(r[2]), "=r"(r[3]) : "r"(addr));
}
__device__ __forceinline__ void mma16816(float* c, const uint32_t* a,
                                         uint32_t b0, uint32_t b1) {
    asm volatile(
        "mma.sync.aligned.m16n8k16.row.col.f32.bf16.bf16.f32 "
        "{%0,%1,%2,%3}, {%4,%5,%6,%7}, {%8,%9}, {%0,%1,%2,%3};"
        : "+f"(c[0]), "+f"(c[1]), "+f"(c[2]), "+f"(c[3])
        : "r"(a[0]), "r"(a[1]), "r"(a[2]), "r"(a[3]), "r"(b0), "r"(b1));
}

// ---------------------------------------------------------------------------
// fp32 -> bf16 hi/lo split
// ---------------------------------------------------------------------------
__global__ __launch_bounds__(256) void cvt_split(
    const float* __restrict__ x, __nv_bfloat16* __restrict__ hi,
    __nv_bfloat16* __restrict__ lo)
{
    int i = (blockIdx.x * 256 + threadIdx.x) * 4;
    float4 v = *(const float4*)(x + i);
    __nv_bfloat16 h0 = __float2bfloat16(v.x);
    __nv_bfloat16 h1 = __float2bfloat16(v.y);
    __nv_bfloat16 h2 = __float2bfloat16(v.z);
    __nv_bfloat16 h3 = __float2bfloat16(v.w);
    __nv_bfloat16 l0 = __float2bfloat16(v.x - __bfloat162float(h0));
    __nv_bfloat16 l1 = __float2bfloat16(v.y - __bfloat162float(h1));
    __nv_bfloat16 l2 = __float2bfloat16(v.z - __bfloat162float(h2));
    __nv_bfloat16 l3 = __float2bfloat16(v.w - __bfloat162float(h3));
    *(__nv_bfloat162*)(hi + i)     = __nv_bfloat162(h0, h1);
    *(__nv_bfloat162*)(hi + i + 2) = __nv_bfloat162(h2, h3);
    *(__nv_bfloat162*)(lo + i)     = __nv_bfloat162(l0, l1);
    *(__nv_bfloat162*)(lo + i + 2) = __nv_bfloat162(l2, l3);
}

// ---------------------------------------------------------------------------
// HMMA GEMM: C[M,N] = (Ah+Al)[M,K] @ (Bh+Bl)[N,K]^T + bias[N]
// Split product Ah*Bh + Ah*Bl + Al*Bh, fp32 register accum.
// Block 128x128, 8 warps (warp tile 32x64), k-tile 32, 3-stage cp.async.
// ---------------------------------------------------------------------------
#define ROWB  80                      // bytes per 32-elem bf16 row (64 + pad)
#define MATB  (128 * ROWB)            // 10240 B per matrix per stage
#define STAGE (4 * MATB)              // Ah, Al, Bh, Bl
#define NSTG  3
#define GSMEM (NSTG * STAGE)          // 122880 B

__global__ __launch_bounds__(256) void gemm_hmma(
    const __nv_bfloat16* __restrict__ Ah, const __nv_bfloat16* __restrict__ Al,
    const __nv_bfloat16* __restrict__ Bh, const __nv_bfloat16* __restrict__ Bl,
    const float* __restrict__ bias, float* __restrict__ C, int M, int N, int K)
{
    extern __shared__ __align__(1024) char sm[];
    const uint32_t sb = smem_u32(sm);
    const int tid = threadIdx.x;
    const int lane = tid & 31, wid = tid >> 5;
    const int warp_m = wid >> 1, warp_n = wid & 1;
    const int bm = blockIdx.y * 128, bn = blockIdx.x * 128;

    // loader mapping: thread t -> row t>>1, chunks (t&1)*2 .. +1 (16B each)
    const int lrw = tid >> 1;
    const int lck = (tid & 1) * 2;
    const __nv_bfloat16* gAh = Ah + (size_t)(bm + lrw) * K + lck * 8;
    const __nv_bfloat16* gAl = Al + (size_t)(bm + lrw) * K + lck * 8;
    const __nv_bfloat16* gBh = Bh + (size_t)(bn + lrw) * K + lck * 8;
    const __nv_bfloat16* gBl = Bl + (size_t)(bn + lrw) * K + lck * 8;
    const uint32_t sAdst = lrw * ROWB + lck * 16;

    const int NKT = K / 32;

    // issue stage loads for k-tile kt into stage s
#define ISSUE(s, kt) do {                                                   \
        const uint32_t so = sb + (s) * STAGE + sAdst;                       \
        const size_t go = (size_t)(kt) * 32;                                \
        cp16(so,                 gAh + go);                                 \
        cp16(so + 16,            gAh + go + 8);                             \
        cp16(so + MATB,          gAl + go);                                 \
        cp16(so + MATB + 16,     gAl + go + 8);                             \
        cp16(so + 2 * MATB,      gBh + go);                                 \
        cp16(so + 2 * MATB + 16, gBh + go + 8);                             \
        cp16(so + 3 * MATB,      gBl + go);                                 \
        cp16(so + 3 * MATB + 16, gBl + go + 8);                             \
        CP_COMMIT();                                                       \
    } while (0)

    ISSUE(0, 0);
    ISSUE(1, 1);

    float c[2][8][4];
#pragma unroll
    for (int i = 0; i < 2; i++)
#pragma unroll
        for (int j = 0; j < 8; j++)
#pragma unroll
            for (int q = 0; q < 4; q++) c[i][j][q] = 0.f;

    // ldsm lane addressing
    const uint32_t frow = lane & 15;           // row within 16-row block
    const uint32_t fkb  = ((lane >> 4) & 1) * 16;  // 0 or +16 B (k half)
    const uint32_t aBase = (warp_m * 32 + frow) * ROWB + fkb;
    const uint32_t bBase = (warp_n * 64 + frow) * ROWB + fkb;

#pragma unroll 1
    for (int kt = 0; kt < NKT; kt++) {
        CP_WAIT(NSTG - 2);
        __syncthreads();
        const uint32_t st = sb + (kt % NSTG) * STAGE;

        if (kt + NSTG - 1 < NKT) ISSUE((kt + NSTG - 1) % NSTG, kt + NSTG - 1);

#pragma unroll
        for (int ks = 0; ks < 2; ks++) {
            const uint32_t ko = ks * 32;
            uint32_t ah[2][4], al_[2][4], bh[4][4], bl[4][4];
#pragma unroll
            for (int mi = 0; mi < 2; mi++) {
                ldsm4(ah[mi],  st + aBase + mi * 16 * ROWB + ko);
                ldsm4(al_[mi], st + MATB + aBase + mi * 16 * ROWB + ko);
            }
#pragma unroll
            for (int nb = 0; nb < 4; nb++) {
                ldsm4(bh[nb], st + 2 * MATB + bBase + nb * 16 * ROWB + ko);
                ldsm4(bl[nb], st + 3 * MATB + bBase + nb * 16 * ROWB + ko);
            }
#pragma unroll
            for (int mi = 0; mi < 2; mi++)
#pragma unroll
                for (int nb = 0; nb < 4; nb++) {
                    // n8 #0 of this n16 block: frag regs {r0, r2}
                    mma16816(c[mi][nb * 2],     ah[mi],  bh[nb][0], bh[nb][2]);
                    mma16816(c[mi][nb * 2],     ah[mi],  bl[nb][0], bl[nb][2]);
                    mma16816(c[mi][nb * 2],     al_[mi], bh[nb][0], bh[nb][2]);
                    // n8 #1: frag regs {r1, r3}
                    mma16816(c[mi][nb * 2 + 1], ah[mi],  bh[nb][1], bh[nb][3]);
                    mma16816(c[mi][nb * 2 + 1], ah[mi],  bl[nb][1], bl[nb][3]);
                    mma16816(c[mi][nb * 2 + 1], al_[mi], bh[nb][1], bh[nb][3]);
                }
        }
        __syncthreads();
    }

    // Epilogue: c frag lane mapping: rows lane/4 (+8), cols (lane%4)*2 (+1)
    const int erow = lane >> 2, ecol = (lane & 3) * 2;
#pragma unroll
    for (int mi = 0; mi < 2; mi++) {
        const int r0 = bm + warp_m * 32 + mi * 16 + erow;
#pragma unroll
        for (int n8 = 0; n8 < 8; n8++) {
            const int cc = bn + warp_n * 64 + n8 * 8 + ecol;
            const float b0 = bias[cc], b1 = bias[cc + 1];
            float2 v0 = {c[mi][n8][0] + b0, c[mi][n8][1] + b1};
            float2 v1 = {c[mi][n8][2] + b0, c[mi][n8][3] + b1};
            *(float2*)(C + (size_t)r0 * N + cc)       = v0;
            *(float2*)(C + (size_t)(r0 + 8) * N + cc) = v1;
        }
    }
#undef ISSUE
}

// ---------------------------------------------------------------------------
// Flash attention (fp32), epilogue writes bf16 hi/lo for the output proj
// ---------------------------------------------------------------------------
#define AST 68

__global__ __launch_bounds__(256) void attn_kernel(
    const float* __restrict__ Q, const float* __restrict__ Kg_,
    const float* __restrict__ V, const float* __restrict__ mult,
    __nv_bfloat16* __restrict__ Oh, __nv_bfloat16* __restrict__ Ol)
{
    extern __shared__ float smf[];
    float* QsT = smf;
    float* KsT = QsT + 64 * AST;
    float* Vs  = KsT + 64 * AST;
    float* PsT = Vs  + 64 * AST;
    float* lb  = PsT + 64 * AST;

    const int qt = blockIdx.x, h = blockIdx.y, b = blockIdx.z;
    const int tid = threadIdx.x;
    const int tx = tid & 15;
    const int ty = tid >> 4;
    const int lr = tid >> 2;
    const int lc = (tid & 3) * 16;

    {
        const float* Qg = Q + ((size_t)(b * NQV + qt * 64 + lr)) * EMBED + h * HD;
#pragma unroll
        for (int i = 0; i < 4; i++) {
            const int d = lc + i * 4;
            float4 v = *(const float4*)(Qg + d);
            QsT[(d + 0) * AST + lr] = v.x * 0.125f;
            QsT[(d + 1) * AST + lr] = v.y * 0.125f;
            QsT[(d + 2) * AST + lr] = v.z * 0.125f;
            QsT[(d + 3) * AST + lr] = v.w * 0.125f;
        }
    }

    float mrow[4], lrow[4], o[4][4];
#pragma unroll
    for (int i = 0; i < 4; i++) {
        mrow[i] = -1e30f; lrow[i] = 0.f;
#pragma unroll
        for (int j = 0; j < 4; j++) o[i][j] = 0.f;
    }

    for (int kt = 0; kt < NKV / 64; kt++) {
        const float* Kr = Kg_ + ((size_t)(b * NKV + kt * 64 + lr)) * EMBED + h * HD;
        const float* Vr = V   + ((size_t)(b * NKV + kt * 64 + lr)) * EMBED + h * HD;
#pragma unroll
        for (int i = 0; i < 4; i++) {
            const int d = lc + i * 4;
            float4 kv = *(const float4*)(Kr + d);
            KsT[(d + 0) * AST + lr] = kv.x;
            KsT[(d + 1) * AST + lr] = kv.y;
            KsT[(d + 2) * AST + lr] = kv.z;
            KsT[(d + 3) * AST + lr] = kv.w;
            float4 vv = *(const float4*)(Vr + d);
            *(float4*)&Vs[lr * AST + d] = vv;
        }
        if (tid < 64)
            lb[tid] = __logf(mult[(size_t)b * NKV + kt * 64 + tid]);
        __syncthreads();

        float s[4][4];
#pragma unroll
        for (int i = 0; i < 4; i++)
#pragma unroll
            for (int j = 0; j < 4; j++) s[i][j] = 0.f;

#pragma unroll 8
        for (int d = 0; d < 64; d++) {
            float4 a  = *(const float4*)&QsT[d * AST + ty * 4];
            float4 bk = *(const float4*)&KsT[d * AST + tx * 4];
            float av[4] = {a.x, a.y, a.z, a.w};
            float bv[4] = {bk.x, bk.y, bk.z, bk.w};
#pragma unroll
            for (int i = 0; i < 4; i++)
#pragma unroll
                for (int j = 0; j < 4; j++)
                    s[i][j] = fmaf(av[i], bv[j], s[i][j]);
        }

        float bj[4];
#pragma unroll
        for (int j = 0; j < 4; j++) bj[j] = lb[tx * 4 + j];
#pragma unroll
        for (int i = 0; i < 4; i++)
#pragma unroll
            for (int j = 0; j < 4; j++) s[i][j] += bj[j];

#pragma unroll
        for (int i = 0; i < 4; i++) {
            float rm = s[i][0];
#pragma unroll
            for (int j = 1; j < 4; j++) rm = fmaxf(rm, s[i][j]);
#pragma unroll
            for (int off = 1; off < 16; off <<= 1)
                rm = fmaxf(rm, __shfl_xor_sync(0xffffffffu, rm, off, 16));
            const float mn = fmaxf(mrow[i], rm);
            const float al = __expf(mrow[i] - mn);
            float rs = 0.f;
#pragma unroll
            for (int j = 0; j < 4; j++) {
                s[i][j] = __expf(s[i][j] - mn);
                rs += s[i][j];
            }
#pragma unroll
            for (int off = 1; off < 16; off <<= 1)
                rs += __shfl_xor_sync(0xffffffffu, rs, off, 16);
            lrow[i] = lrow[i] * al + rs;
            mrow[i] = mn;
#pragma unroll
            for (int j = 0; j < 4; j++) o[i][j] *= al;
        }

#pragma unroll
        for (int i = 0; i < 4; i++)
#pragma unroll
            for (int j = 0; j < 4; j++)
                PsT[(tx * 4 + j) * AST + ty * 4 + i] = s[i][j];
        __syncthreads();

#pragma unroll 8
        for (int k = 0; k < 64; k++) {
            float4 p  = *(const float4*)&PsT[k * AST + ty * 4];
            float4 vv = *(const float4*)&Vs[k * AST + tx * 4];
            float pv[4] = {p.x, p.y, p.z, p.w};
            float vvv[4] = {vv.x, vv.y, vv.z, vv.w};
#pragma unroll
            for (int i = 0; i < 4; i++)
#pragma unroll
                for (int j = 0; j < 4; j++)
                    o[i][j] = fmaf(pv[i], vvv[j], o[i][j]);
        }
        __syncthreads();
    }

#pragma unroll
    for (int i = 0; i < 4; i++) {
        const float inv = 1.f / lrow[i];
        const size_t base = ((size_t)(b * NQV + qt * 64 + ty * 4 + i)) * EMBED
                            + h * HD + tx * 4;
#pragma unroll
        for (int j = 0; j < 4; j++) {
            float vout = o[i][j] * inv;
            __nv_bfloat16 hh = __float2bfloat16(vout);
            Oh[base + j] = hh;
            Ol[base + j] = __float2bfloat16(vout - __bfloat162float(hh));
        }
    }
}

// ---------------------------------------------------------------------------
extern "C" void kernel_launch(void* const* d_in, const int* in_sizes, int n_in,
                              void* d_out, int out_size)
{
    const float* query = (const float*)d_in[0];
    const float* key   = (const float*)d_in[1];
    const float* value = (const float*)d_in[2];
    const float* mult  = (const float*)d_in[3];
    const float* wq_w  = (const float*)d_in[4];
    const float* wq_b  = (const float*)d_in[5];
    const float* wk_w  = (const float*)d_in[6];
    const float* wk_b  = (const float*)d_in[7];
    const float* wv_w  = (const float*)d_in[8];
    const float* wv_b  = (const float*)d_in[9];
    const float* wo_w  = (const float*)d_in[10];
    const float* wo_b  = (const float*)d_in[11];
    float* out = (float*)d_out;

    float *gq, *gk, *gv;
    cudaGetSymbolAddress((void**)&gq, g_Q);
    cudaGetSymbolAddress((void**)&gk, g_K);
    cudaGetSymbolAddress((void**)&gv, g_V);
    __nv_bfloat16 *qh,*ql,*kh,*kl,*vh,*vl,*aoh,*aol;
    __nv_bfloat16 *wqh,*wql,*wkh,*wkl,*wvh,*wvl,*woh,*wol;
    cudaGetSymbolAddress((void**)&qh, g_qh);  cudaGetSymbolAddress((void**)&ql, g_ql);
    cudaGetSymbolAddress((void**)&kh, g_kh);  cudaGetSymbolAddress((void**)&kl, g_kl);
    cudaGetSymbolAddress((void**)&vh, g_vh);  cudaGetSymbolAddress((void**)&vl, g_vl);
    cudaGetSymbolAddress((void**)&aoh, g_aoh); cudaGetSymbolAddress((void**)&aol, g_aol);
    cudaGetSymbolAddress((void**)&wqh, g_wqh); cudaGetSymbolAddress((void**)&wql, g_wql);
    cudaGetSymbolAddress((void**)&wkh, g_wkh); cudaGetSymbolAddress((void**)&wkl, g_wkl);
    cudaGetSymbolAddress((void**)&wvh, g_wvh); cudaGetSymbolAddress((void**)&wvl, g_wvl);
    cudaGetSymbolAddress((void**)&woh, g_woh); cudaGetSymbolAddress((void**)&wol, g_wol);

    cudaFuncSetAttribute(gemm_hmma, cudaFuncAttributeMaxDynamicSharedMemorySize, GSMEM);
    const int smem_attn = (4 * 64 * AST + 64) * (int)sizeof(float);
    cudaFuncSetAttribute(attn_kernel,
                         cudaFuncAttributeMaxDynamicSharedMemorySize, smem_attn);

    const int MQ = BATCH * NQV;   // 4096
    const int MK = BATCH * NKV;   // 8192
    const int NW = EMBED * EMBED;

    // bf16 hi/lo conversions
    cvt_split<<<MQ * EMBED / 1024, 256>>>(query, qh, ql);
    cvt_split<<<MK * EMBED / 1024, 256>>>(key,   kh, kl);
    cvt_split<<<MK * EMBED / 1024, 256>>>(value, vh, vl);
    cvt_split<<<NW / 1024, 256>>>(wq_w, wqh, wql);
    cvt_split<<<NW / 1024, 256>>>(wk_w, wkh, wkl);
    cvt_split<<<NW / 1024, 256>>>(wv_w, wvh, wvl);
    cvt_split<<<NW / 1024, 256>>>(wo_w, woh, wol);

    // Projections (HMMA tensor cores, bf16 split)
    gemm_hmma<<<dim3(EMBED / 128, MQ / 128), 256, GSMEM>>>(qh, ql, wqh, wql, wq_b, gq, MQ, EMBED, EMBED);
    gemm_hmma<<<dim3(EMBED / 128, MK / 128), 256, GSMEM>>>(kh, kl, wkh, wkl, wk_b, gk, MK, EMBED, EMBED);
    gemm_hmma<<<dim3(EMBED / 128, MK / 128), 256, GSMEM>>>(vh, vl, wvh, wvl, wv_b, gv, MK, EMBED, EMBED);

    // Attention (fp32) -> bf16 hi/lo out
    attn_kernel<<<dim3(NQV / 64, NH, BATCH), 256, smem_attn>>>(gq, gk, gv, mult, aoh, aol);

    // Output projection
    gemm_hmma<<<dim3(EMBED / 128, MQ / 128), 256, GSMEM>>>(aoh, aol, woh, wol, wo_b, out, MQ, EMBED, EMBED);
}

// round 4
// speedup vs baseline: 2.3841x; 1.6185x over previous
#include <cuda_runtime.h>
#include <cuda_bf16.h>
#include <math.h>
#include <stdint.h>

#define EMBED 1024
#define NQV   1024
#define NKV   2048
#define BATCH 4
#define NH    16
#define HD    64

// ---------------------------------------------------------------------------
// Scratch (__device__ globals — allocation-free rule)
// ---------------------------------------------------------------------------
__device__ float g_Q[BATCH * NQV * EMBED];
__device__ float g_K[BATCH * NKV * EMBED];
__device__ float g_V[BATCH * NKV * EMBED];
__device__ float g_lb[BATCH * NKV];

__device__ __nv_bfloat16 g_qh[BATCH * NQV * EMBED], g_ql[BATCH * NQV * EMBED];
__device__ __nv_bfloat16 g_kh[BATCH * NKV * EMBED], g_kl[BATCH * NKV * EMBED];
__device__ __nv_bfloat16 g_vh[BATCH * NKV * EMBED], g_vl[BATCH * NKV * EMBED];
__device__ __nv_bfloat16 g_vth[BATCH * NH * HD * NKV], g_vtl[BATCH * NH * HD * NKV];
__device__ __nv_bfloat16 g_aoh[BATCH * NQV * EMBED], g_aol[BATCH * NQV * EMBED];
__device__ __nv_bfloat16 g_wqh[EMBED * EMBED], g_wql[EMBED * EMBED];
__device__ __nv_bfloat16 g_wkh[EMBED * EMBED], g_wkl[EMBED * EMBED];
__device__ __nv_bfloat16 g_wvh[EMBED * EMBED], g_wvl[EMBED * EMBED];
__device__ __nv_bfloat16 g_woh[EMBED * EMBED], g_wol[EMBED * EMBED];

// ---------------------------------------------------------------------------
// PTX helpers (sm_80-compatible ISA: this toolchain is compute_103 w/o 'a')
// ---------------------------------------------------------------------------
__device__ __forceinline__ uint32_t smem_u32(const void* p) {
    uint32_t a;
    asm("{ .reg .u64 t; cvta.to.shared.u64 t, %1; cvt.u32.u64 %0, t; }"
        : "=r"(a) : "l"(p));
    return a;
}
__device__ __forceinline__ void cp16(uint32_t dst, const void* src) {
    asm volatile("cp.async.cg.shared.global [%0], [%1], 16;"
                 :: "r"(dst), "l"(src) : "memory");
}
#define CP_COMMIT() asm volatile("cp.async.commit_group;" ::: "memory")
#define CP_WAIT(n)  asm volatile("cp.async.wait_group %0;" :: "n"(n) : "memory")

__device__ __forceinline__ void ldsm4(uint32_t* r, uint32_t addr) {
    asm volatile("ldmatrix.sync.aligned.m8n8.x4.shared.b16 {%0,%1,%2,%3}, [%4];"
                 : "=r"(r[0]), "=r"(r[1]), "=r"(r[2]), "=r"(r[3]) : "r"(addr));
}
__device__ __forceinline__ void mma16816(float* c, const uint32_t* a,
                                         uint32_t b0, uint32_t b1) {
    asm volatile(
        "mma.sync.aligned.m16n8k16.row.col.f32.bf16.bf16.f32 "
        "{%0,%1,%2,%3}, {%4,%5,%6,%7}, {%8,%9}, {%0,%1,%2,%3};"
        : "+f"(c[0]), "+f"(c[1]), "+f"(c[2]), "+f"(c[3])
        : "r"(a[0]), "r"(a[1]), "r"(a[2]), "r"(a[3]), "r"(b0), "r"(b1));
}
__device__ __forceinline__ uint32_t packbf(float lo, float hi) {
    uint32_t d;
    asm("cvt.rn.bf16x2.f32 %0, %1, %2;" : "=r"(d) : "f"(hi), "f"(lo));
    return d;
}

// ---------------------------------------------------------------------------
// fp32 -> bf16 hi/lo split
// ---------------------------------------------------------------------------
__global__ __launch_bounds__(256) void cvt_split(
    const float* __restrict__ x, __nv_bfloat16* __restrict__ hi,
    __nv_bfloat16* __restrict__ lo)
{
    int i = (blockIdx.x * 256 + threadIdx.x) * 4;
    float4 v = *(const float4*)(x + i);
    __nv_bfloat16 h0 = __float2bfloat16(v.x);
    __nv_bfloat16 h1 = __float2bfloat16(v.y);
    __nv_bfloat16 h2 = __float2bfloat16(v.z);
    __nv_bfloat16 h3 = __float2bfloat16(v.w);
    __nv_bfloat16 l0 = __float2bfloat16(v.x - __bfloat162float(h0));
    __nv_bfloat16 l1 = __float2bfloat16(v.y - __bfloat162float(h1));
    __nv_bfloat16 l2 = __float2bfloat16(v.z - __bfloat162float(h2));
    __nv_bfloat16 l3 = __float2bfloat16(v.w - __bfloat162float(h3));
    *(__nv_bfloat162*)(hi + i)     = __nv_bfloat162(h0, h1);
    *(__nv_bfloat162*)(hi + i + 2) = __nv_bfloat162(h2, h3);
    *(__nv_bfloat162*)(lo + i)     = __nv_bfloat162(l0, l1);
    *(__nv_bfloat162*)(lo + i + 2) = __nv_bfloat162(l2, l3);
}

// log of key multiplicities
__global__ __launch_bounds__(256) void log_mult(const float* __restrict__ m,
                                                float* __restrict__ lb) {
    int i = blockIdx.x * 256 + threadIdx.x;
    lb[i] = __logf(m[i]);
}

// V fp32 [b][key][embed] -> transposed bf16 hi/lo [b][h][d][key]
__global__ void transpose_split_v(const float* __restrict__ V,
                                  __nv_bfloat16* __restrict__ vth,
                                  __nv_bfloat16* __restrict__ vtl)
{
    __shared__ float t[32][33];
    const int x = threadIdx.x, y = threadIdx.y;
    const int key0 = blockIdx.x * 32, e0 = blockIdx.y * 32, b = blockIdx.z;
#pragma unroll
    for (int i = 0; i < 4; i++)
        t[y + i * 8][x] = V[((size_t)(b * NKV + key0 + y + i * 8)) * EMBED + e0 + x];
    __syncthreads();
#pragma unroll
    for (int i = 0; i < 4; i++) {
        const int e = e0 + y + i * 8;
        const size_t o = ((size_t)((b * NH + (e >> 6)) * HD + (e & 63))) * NKV + key0 + x;
        float v = t[x][y + i * 8];
        __nv_bfloat16 h = __float2bfloat16(v);
        vth[o] = h;
        vtl[o] = __float2bfloat16(v - __bfloat162float(h));
    }
}

// ---------------------------------------------------------------------------
// HMMA GEMM: C[M,N] = (Ah+Al)[M,K] @ (Bh+Bl)[N,K]^T + bias[N]
// ---------------------------------------------------------------------------
#define ROWB  80
#define MATB  (128 * ROWB)
#define STAGE (4 * MATB)
#define NSTG  3
#define GSMEM (NSTG * STAGE)

__global__ __launch_bounds__(256) void gemm_hmma(
    const __nv_bfloat16* __restrict__ Ah, const __nv_bfloat16* __restrict__ Al,
    const __nv_bfloat16* __restrict__ Bh, const __nv_bfloat16* __restrict__ Bl,
    const float* __restrict__ bias, float* __restrict__ C, int M, int N, int K)
{
    extern __shared__ __align__(1024) char sm[];
    const uint32_t sb = smem_u32(sm);
    const int tid = threadIdx.x;
    const int lane = tid & 31, wid = tid >> 5;
    const int warp_m = wid >> 1, warp_n = wid & 1;
    const int bm = blockIdx.y * 128, bn = blockIdx.x * 128;

    const int lrw = tid >> 1;
    const int lck = (tid & 1) * 2;
    const __nv_bfloat16* gAh = Ah + (size_t)(bm + lrw) * K + lck * 8;
    const __nv_bfloat16* gAl = Al + (size_t)(bm + lrw) * K + lck * 8;
    const __nv_bfloat16* gBh = Bh + (size_t)(bn + lrw) * K + lck * 8;
    const __nv_bfloat16* gBl = Bl + (size_t)(bn + lrw) * K + lck * 8;
    const uint32_t sAdst = lrw * ROWB + lck * 16;

    const int NKT = K / 32;

#define ISSUE(s, kt) do {                                                   \
        const uint32_t so = sb + (s) * STAGE + sAdst;                       \
        const size_t go = (size_t)(kt) * 32;                                \
        cp16(so,                 gAh + go);                                 \
        cp16(so + 16,            gAh + go + 8);                             \
        cp16(so + MATB,          gAl + go);                                 \
        cp16(so + MATB + 16,     gAl + go + 8);                             \
        cp16(so + 2 * MATB,      gBh + go);                                 \
        cp16(so + 2 * MATB + 16, gBh + go + 8);                             \
        cp16(so + 3 * MATB,      gBl + go);                                 \
        cp16(so + 3 * MATB + 16, gBl + go + 8);                             \
        CP_COMMIT();                                                       \
    } while (0)

    ISSUE(0, 0);
    ISSUE(1, 1);

    float c[2][8][4];
#pragma unroll
    for (int i = 0; i < 2; i++)
#pragma unroll
        for (int j = 0; j < 8; j++)
#pragma unroll
            for (int q = 0; q < 4; q++) c[i][j][q] = 0.f;

    const uint32_t frow = lane & 15;
    const uint32_t fkb  = ((lane >> 4) & 1) * 16;
    const uint32_t aBase = (warp_m * 32 + frow) * ROWB + fkb;
    const uint32_t bBase = (warp_n * 64 + frow) * ROWB + fkb;

#pragma unroll 1
    for (int kt = 0; kt < NKT; kt++) {
        CP_WAIT(NSTG - 2);
        __syncthreads();
        const uint32_t st = sb + (kt % NSTG) * STAGE;

        if (kt + NSTG - 1 < NKT) ISSUE((kt + NSTG - 1) % NSTG, kt + NSTG - 1);

#pragma unroll
        for (int ks = 0; ks < 2; ks++) {
            const uint32_t ko = ks * 32;
            uint32_t ah[2][4], al_[2][4], bh[4][4], bl[4][4];
#pragma unroll
            for (int mi = 0; mi < 2; mi++) {
                ldsm4(ah[mi],  st + aBase + mi * 16 * ROWB + ko);
                ldsm4(al_[mi], st + MATB + aBase + mi * 16 * ROWB + ko);
            }
#pragma unroll
            for (int nb = 0; nb < 4; nb++) {
                ldsm4(bh[nb], st + 2 * MATB + bBase + nb * 16 * ROWB + ko);
                ldsm4(bl[nb], st + 3 * MATB + bBase + nb * 16 * ROWB + ko);
            }
#pragma unroll
            for (int mi = 0; mi < 2; mi++)
#pragma unroll
                for (int nb = 0; nb < 4; nb++) {
                    mma16816(c[mi][nb * 2],     ah[mi],  bh[nb][0], bh[nb][2]);
                    mma16816(c[mi][nb * 2],     ah[mi],  bl[nb][0], bl[nb][2]);
                    mma16816(c[mi][nb * 2],     al_[mi], bh[nb][0], bh[nb][2]);
                    mma16816(c[mi][nb * 2 + 1], ah[mi],  bh[nb][1], bh[nb][3]);
                    mma16816(c[mi][nb * 2 + 1], ah[mi],  bl[nb][1], bl[nb][3]);
                    mma16816(c[mi][nb * 2 + 1], al_[mi], bh[nb][1], bh[nb][3]);
                }
        }
        __syncthreads();
    }

    const int erow = lane >> 2, ecol = (lane & 3) * 2;
#pragma unroll
    for (int mi = 0; mi < 2; mi++) {
        const int r0 = bm + warp_m * 32 + mi * 16 + erow;
#pragma unroll
        for (int n8 = 0; n8 < 8; n8++) {
            const int cc = bn + warp_n * 64 + n8 * 8 + ecol;
            const float b0 = bias[cc], b1 = bias[cc + 1];
            float2 v0 = {c[mi][n8][0] + b0, c[mi][n8][1] + b1};
            float2 v1 = {c[mi][n8][2] + b0, c[mi][n8][3] + b1};
            *(float2*)(C + (size_t)r0 * N + cc)       = v0;
            *(float2*)(C + (size_t)(r0 + 8) * N + cc) = v1;
        }
    }
#undef ISSUE
}

// ---------------------------------------------------------------------------
// HMMA flash attention, bf16 split: softmax(QK^T/8 + log m) V
// Block: 128 q-rows (8 warps x 16), 64-key tiles, double-buffered cp.async.
// ---------------------------------------------------------------------------
#define QROW 144                       // 64 bf16 (128B) + 16B pad
#define SQ_L   (128 * QROW)            // 18432
#define SQ_SZ  (2 * 128 * QROW)        // 36864
#define SK_L   (64 * QROW)             // within stage: 9216
#define SVT_H  (2 * 64 * QROW)         // 18432
#define SVT_L  (3 * 64 * QROW)         // 27648
#define SLB    (4 * 64 * QROW)         // 36864
#define STG_SZ (4 * 64 * QROW + 256)   // 37120
#define ASMEM  (SQ_SZ + 2 * STG_SZ)    // 111104

__global__ __launch_bounds__(256) void attn_hmma(
    const float* __restrict__ Q, const __nv_bfloat16* __restrict__ Kh,
    const __nv_bfloat16* __restrict__ Kl, const __nv_bfloat16* __restrict__ VTh,
    const __nv_bfloat16* __restrict__ VTl, const float* __restrict__ lbG,
    __nv_bfloat16* __restrict__ Oh, __nv_bfloat16* __restrict__ Ol)
{
    extern __shared__ __align__(1024) char sm[];
    const uint32_t sb = smem_u32(sm);
    const int qt = blockIdx.x, h = blockIdx.y, b = blockIdx.z;
    const int tid = threadIdx.x;
    const int lane = tid & 31, wid = tid >> 5;

    // ---- load Q tile (fp32 -> scaled bf16 hi/lo, row-major [q][d]) ----
    {
        const int row = tid >> 1, half = (tid & 1) * 32;
        const float* Qg = Q + ((size_t)(b * NQV + qt * 128 + row)) * EMBED + h * HD + half;
        char* dh = sm + row * QROW + half * 2;
        char* dl = sm + SQ_L + row * QROW + half * 2;
#pragma unroll
        for (int i = 0; i < 8; i++) {
            float4 v = *(const float4*)(Qg + i * 4);
            float f0 = v.x * 0.125f, f1 = v.y * 0.125f;
            float f2 = v.z * 0.125f, f3 = v.w * 0.125f;
            __nv_bfloat16 h0 = __float2bfloat16(f0), h1 = __float2bfloat16(f1);
            __nv_bfloat16 h2 = __float2bfloat16(f2), h3 = __float2bfloat16(f3);
            *(__nv_bfloat162*)(dh + i * 8)     = __nv_bfloat162(h0, h1);
            *(__nv_bfloat162*)(dh + i * 8 + 4) = __nv_bfloat162(h2, h3);
            *(__nv_bfloat162*)(dl + i * 8) =
                __nv_bfloat162(__float2bfloat16(f0 - __bfloat162float(h0)),
                               __float2bfloat16(f1 - __bfloat162float(h1)));
            *(__nv_bfloat162*)(dl + i * 8 + 4) =
                __nv_bfloat162(__float2bfloat16(f2 - __bfloat162float(h2)),
                               __float2bfloat16(f3 - __bfloat162float(h3)));
        }
    }

    // ---- stage loader ----
    const int srow = tid >> 2, scq = tid & 3;
    const __nv_bfloat16* gK_h = Kh + ((size_t)(b * NKV + srow)) * EMBED + h * HD + scq * 16;
    const __nv_bfloat16* gK_l = Kl + ((size_t)(b * NKV + srow)) * EMBED + h * HD + scq * 16;
    const __nv_bfloat16* gV_h = VTh + ((size_t)((b * NH + h) * HD + srow)) * NKV + scq * 16;
    const __nv_bfloat16* gV_l = VTl + ((size_t)((b * NH + h) * HD + srow)) * NKV + scq * 16;
    const uint32_t sdst = srow * QROW + scq * 32;
    const float* gLB = lbG + (size_t)b * NKV;

#define AISSUE(s, kt) do {                                                  \
        const uint32_t so = sb + SQ_SZ + (s) * STG_SZ;                      \
        const size_t koK = (size_t)(kt) * 64 * EMBED;                       \
        const size_t koV = (size_t)(kt) * 64;                               \
        cp16(so + sdst,              gK_h + koK);                           \
        cp16(so + sdst + 16,         gK_h + koK + 8);                       \
        cp16(so + SK_L + sdst,       gK_l + koK);                           \
        cp16(so + SK_L + sdst + 16,  gK_l + koK + 8);                       \
        cp16(so + SVT_H + sdst,      gV_h + koV);                           \
        cp16(so + SVT_H + sdst + 16, gV_h + koV + 8);                       \
        cp16(so + SVT_L + sdst,      gV_l + koV);                           \
        cp16(so + SVT_L + sdst + 16, gV_l + koV + 8);                       \
        if (tid < 16) cp16(so + SLB + tid * 16, gLB + (kt) * 64 + tid * 4); \
        CP_COMMIT();                                                       \
    } while (0)

    AISSUE(0, 0);
    __syncthreads();   // Q tile visible

    // ---- cache Q hi fragments ----
    const uint32_t frow = lane & 15;
    const uint32_t fkb  = ((lane >> 4) & 1) * 16;
    const uint32_t qBase = (wid * 16 + frow) * QROW + fkb;
    uint32_t qh[4][4];
#pragma unroll
    for (int ks = 0; ks < 4; ks++) ldsm4(qh[ks], sb + qBase + ks * 32);

    float o[8][4];
#pragma unroll
    for (int j = 0; j < 8; j++)
#pragma unroll
        for (int q = 0; q < 4; q++) o[j][q] = 0.f;
    float m0 = -1e30f, m1 = -1e30f, l0 = 0.f, l1 = 0.f;

    const int NT = NKV / 64;
#pragma unroll 1
    for (int kt = 0; kt < NT; kt++) {
        if (kt + 1 < NT) { AISSUE((kt + 1) & 1, kt + 1); CP_WAIT(1); }
        else             { CP_WAIT(0); }
        __syncthreads();
        const uint32_t st = sb + SQ_SZ + (kt & 1) * STG_SZ;

        // ---- S = Q K^T ----
        float c[8][4];
#pragma unroll
        for (int j = 0; j < 8; j++)
#pragma unroll
            for (int q = 0; q < 4; q++) c[j][q] = 0.f;

#pragma unroll
        for (int ks = 0; ks < 4; ks++) {
            uint32_t ql_[4];
            ldsm4(ql_, sb + SQ_L + qBase + ks * 32);
#pragma unroll
            for (int nb = 0; nb < 4; nb++) {
                uint32_t kh[4], kl[4];
                const uint32_t ka = st + (nb * 16 + frow) * QROW + fkb + ks * 32;
                ldsm4(kh, ka);
                ldsm4(kl, ka + SK_L);
                mma16816(c[nb * 2], qh[ks], kh[0], kh[2]);
                mma16816(c[nb * 2], qh[ks], kl[0], kl[2]);
                mma16816(c[nb * 2], ql_,    kh[0], kh[2]);
                mma16816(c[nb * 2 + 1], qh[ks], kh[1], kh[3]);
                mma16816(c[nb * 2 + 1], qh[ks], kl[1], kl[3]);
                mma16816(c[nb * 2 + 1], ql_,    kh[1], kh[3]);
            }
        }

        // ---- + log multiplicity ----
        const float* lbs = (const float*)(sm + (st - sb) + SLB);
#pragma unroll
        for (int j = 0; j < 8; j++) {
            float2 lb2 = *(const float2*)(lbs + j * 8 + (lane & 3) * 2);
            c[j][0] += lb2.x; c[j][1] += lb2.y;
            c[j][2] += lb2.x; c[j][3] += lb2.y;
        }

        // ---- online softmax (rows lane/4 and lane/4+8) ----
        float rm0 = -1e30f, rm1 = -1e30f;
#pragma unroll
        for (int j = 0; j < 8; j++) {
            rm0 = fmaxf(rm0, fmaxf(c[j][0], c[j][1]));
            rm1 = fmaxf(rm1, fmaxf(c[j][2], c[j][3]));
        }
#pragma unroll
        for (int off = 1; off < 4; off <<= 1) {
            rm0 = fmaxf(rm0, __shfl_xor_sync(0xffffffffu, rm0, off));
            rm1 = fmaxf(rm1, __shfl_xor_sync(0xffffffffu, rm1, off));
        }
        const float mn0 = fmaxf(m0, rm0), mn1 = fmaxf(m1, rm1);
        const float al0 = __expf(m0 - mn0), al1 = __expf(m1 - mn1);
        float rs0 = 0.f, rs1 = 0.f;
#pragma unroll
        for (int j = 0; j < 8; j++) {
            c[j][0] = __expf(c[j][0] - mn0); rs0 += c[j][0];
            c[j][1] = __expf(c[j][1] - mn0); rs0 += c[j][1];
            c[j][2] = __expf(c[j][2] - mn1); rs1 += c[j][2];
            c[j][3] = __expf(c[j][3] - mn1); rs1 += c[j][3];
        }
#pragma unroll
        for (int off = 1; off < 4; off <<= 1) {
            rs0 += __shfl_xor_sync(0xffffffffu, rs0, off);
            rs1 += __shfl_xor_sync(0xffffffffu, rs1, off);
        }
        l0 = l0 * al0 + rs0;  m0 = mn0;
        l1 = l1 * al1 + rs1;  m1 = mn1;
#pragma unroll
        for (int j = 0; j < 8; j++) {
            o[j][0] *= al0; o[j][1] *= al0;
            o[j][2] *= al1; o[j][3] *= al1;
        }

        // ---- O += P V (P split hi/lo in registers) ----
#pragma unroll
        for (int kk = 0; kk < 4; kk++) {
            const int j0 = 2 * kk, j1 = 2 * kk + 1;
            float ph[8], pl[8];
            const float pv[8] = {c[j0][0], c[j0][1], c[j0][2], c[j0][3],
                                 c[j1][0], c[j1][1], c[j1][2], c[j1][3]};
#pragma unroll
            for (int q = 0; q < 8; q++) {
                ph[q] = __bfloat162float(__float2bfloat16(pv[q]));
                pl[q] = pv[q] - ph[q];
            }
            uint32_t ah[4], al_[4];
            ah[0] = packbf(ph[0], ph[1]);  ah[1] = packbf(ph[2], ph[3]);
            ah[2] = packbf(ph[4], ph[5]);  ah[3] = packbf(ph[6], ph[7]);
            al_[0] = packbf(pl[0], pl[1]); al_[1] = packbf(pl[2], pl[3]);
            al_[2] = packbf(pl[4], pl[5]); al_[3] = packbf(pl[6], pl[7]);
#pragma unroll
            for (int nb = 0; nb < 4; nb++) {
                uint32_t vh[4], vl[4];
                const uint32_t va = st + SVT_H + (nb * 16 + frow) * QROW + fkb + kk * 32;
                ldsm4(vh, va);
                ldsm4(vl, va + (SVT_L - SVT_H));
                mma16816(o[nb * 2], ah,  vh[0], vh[2]);
                mma16816(o[nb * 2], al_, vh[0], vh[2]);
                mma16816(o[nb * 2], ah,  vl[0], vl[2]);
                mma16816(o[nb * 2 + 1], ah,  vh[1], vh[3]);
                mma16816(o[nb * 2 + 1], al_, vh[1], vh[3]);
                mma16816(o[nb * 2 + 1], ah,  vl[1], vl[3]);
            }
        }
        __syncthreads();
    }

    // ---- epilogue: normalize, write bf16 hi/lo ----
    const float inv0 = 1.f / l0, inv1 = 1.f / l1;
    const int r0 = qt * 128 + wid * 16 + (lane >> 2);
    const int cc0 = h * HD + (lane & 3) * 2;
#pragma unroll
    for (int j = 0; j < 8; j++) {
        const int col = cc0 + j * 8;
        {
            float v0 = o[j][0] * inv0, v1 = o[j][1] * inv0;
            __nv_bfloat16 h0 = __float2bfloat16(v0), h1 = __float2bfloat16(v1);
            size_t idx = ((size_t)(b * NQV + r0)) * EMBED + col;
            *(__nv_bfloat162*)(Oh + idx) = __nv_bfloat162(h0, h1);
            *(__nv_bfloat162*)(Ol + idx) =
                __nv_bfloat162(__float2bfloat16(v0 - __bfloat162float(h0)),
                               __float2bfloat16(v1 - __bfloat162float(h1)));
        }
        {
            float v0 = o[j][2] * inv1, v1 = o[j][3] * inv1;
            __nv_bfloat16 h0 = __float2bfloat16(v0), h1 = __float2bfloat16(v1);
            size_t idx = ((size_t)(b * NQV + r0 + 8)) * EMBED + col;
            *(__nv_bfloat162*)(Oh + idx) = __nv_bfloat162(h0, h1);
            *(__nv_bfloat162*)(Ol + idx) =
                __nv_bfloat162(__float2bfloat16(v0 - __bfloat162float(h0)),
                               __float2bfloat16(v1 - __bfloat162float(h1)));
        }
    }
#undef AISSUE
}

// ---------------------------------------------------------------------------
extern "C" void kernel_launch(void* const* d_in, const int* in_sizes, int n_in,
                              void* d_out, int out_size)
{
    const float* query = (const float*)d_in[0];
    const float* key   = (const float*)d_in[1];
    const float* value = (const float*)d_in[2];
    const float* mult  = (const float*)d_in[3];
    const float* wq_w  = (const float*)d_in[4];
    const float* wq_b  = (const float*)d_in[5];
    const float* wk_w  = (const float*)d_in[6];
    const float* wk_b  = (const float*)d_in[7];
    const float* wv_w  = (const float*)d_in[8];
    const float* wv_b  = (const float*)d_in[9];
    const float* wo_w  = (const float*)d_in[10];
    const float* wo_b  = (const float*)d_in[11];
    float* out = (float*)d_out;

    float *gq, *gk, *gv, *glb;
    cudaGetSymbolAddress((void**)&gq, g_Q);
    cudaGetSymbolAddress((void**)&gk, g_K);
    cudaGetSymbolAddress((void**)&gv, g_V);
    cudaGetSymbolAddress((void**)&glb, g_lb);
    __nv_bfloat16 *qh,*ql,*kh,*kl,*vh,*vl,*vth,*vtl,*aoh,*aol;
    __nv_bfloat16 *wqh,*wql,*wkh,*wkl,*wvh,*wvl,*woh,*wol;
    cudaGetSymbolAddress((void**)&qh, g_qh);  cudaGetSymbolAddress((void**)&ql, g_ql);
    cudaGetSymbolAddress((void**)&kh, g_kh);  cudaGetSymbolAddress((void**)&kl, g_kl);
    cudaGetSymbolAddress((void**)&vh, g_vh);  cudaGetSymbolAddress((void**)&vl, g_vl);
    cudaGetSymbolAddress((void**)&vth, g_vth); cudaGetSymbolAddress((void**)&vtl, g_vtl);
    cudaGetSymbolAddress((void**)&aoh, g_aoh); cudaGetSymbolAddress((void**)&aol, g_aol);
    cudaGetSymbolAddress((void**)&wqh, g_wqh); cudaGetSymbolAddress((void**)&wql, g_wql);
    cudaGetSymbolAddress((void**)&wkh, g_wkh); cudaGetSymbolAddress((void**)&wkl, g_wkl);
    cudaGetSymbolAddress((void**)&wvh, g_wvh); cudaGetSymbolAddress((void**)&wvl, g_wvl);
    cudaGetSymbolAddress((void**)&woh, g_woh); cudaGetSymbolAddress((void**)&wol, g_wol);

    cudaFuncSetAttribute(gemm_hmma, cudaFuncAttributeMaxDynamicSharedMemorySize, GSMEM);
    cudaFuncSetAttribute(attn_hmma, cudaFuncAttributeMaxDynamicSharedMemorySize, ASMEM);

    const int MQ = BATCH * NQV;
    const int MK = BATCH * NKV;
    const int NW = EMBED * EMBED;

    // input + weight conversions
    cvt_split<<<MQ * EMBED / 1024, 256>>>(query, qh, ql);
    cvt_split<<<MK * EMBED / 1024, 256>>>(key,   kh, kl);
    cvt_split<<<MK * EMBED / 1024, 256>>>(value, vh, vl);
    cvt_split<<<NW / 1024, 256>>>(wq_w, wqh, wql);
    cvt_split<<<NW / 1024, 256>>>(wk_w, wkh, wkl);
    cvt_split<<<NW / 1024, 256>>>(wv_w, wvh, wvl);
    cvt_split<<<NW / 1024, 256>>>(wo_w, woh, wol);
    log_mult<<<MK / 256, 256>>>(mult, glb);

    // projections
    gemm_hmma<<<dim3(EMBED / 128, MQ / 128), 256, GSMEM>>>(qh, ql, wqh, wql, wq_b, gq, MQ, EMBED, EMBED);
    gemm_hmma<<<dim3(EMBED / 128, MK / 128), 256, GSMEM>>>(kh, kl, wkh, wkl, wk_b, gk, MK, EMBED, EMBED);
    gemm_hmma<<<dim3(EMBED / 128, MK / 128), 256, GSMEM>>>(vh, vl, wvh, wvl, wv_b, gv, MK, EMBED, EMBED);

    // projected K -> bf16 split (reuse kh/kl); projected V -> transposed split
    cvt_split<<<MK * EMBED / 1024, 256>>>(gk, kh, kl);
    transpose_split_v<<<dim3(NKV / 32, EMBED / 32, BATCH), dim3(32, 8)>>>(gv, vth, vtl);

    // attention (HMMA)
    attn_hmma<<<dim3(NQV / 128, NH, BATCH), 256, ASMEM>>>(gq, kh, kl, vth, vtl, glb, aoh, aol);

    // output projection
    gemm_hmma<<<dim3(EMBED / 128, MQ / 128), 256, GSMEM>>>(aoh, aol, woh, wol, wo_b, out, MQ, EMBED, EMBED);
}

// round 5
// speedup vs baseline: 2.5712x; 1.0785x over previous
#include <cuda_runtime.h>
#include <cuda_bf16.h>
#include <math.h>
#include <stdint.h>

#define EMBED 1024
#define NQV   1024
#define NKV   2048
#define BATCH 4
#define NH    16
#define HD    64

// ---------------------------------------------------------------------------
// Scratch (__device__ globals — allocation-free rule)
// ---------------------------------------------------------------------------
__device__ float g_V[BATCH * NKV * EMBED];
__device__ float g_lb[BATCH * NKV];

// input splits
__device__ __nv_bfloat16 g_qh[BATCH * NQV * EMBED], g_ql[BATCH * NQV * EMBED];
__device__ __nv_bfloat16 g_kh[BATCH * NKV * EMBED], g_kl[BATCH * NKV * EMBED];
__device__ __nv_bfloat16 g_vh[BATCH * NKV * EMBED], g_vl[BATCH * NKV * EMBED];
// projected activations (split)
__device__ __nv_bfloat16 g_qsh[BATCH * NQV * EMBED], g_qsl[BATCH * NQV * EMBED];
__device__ __nv_bfloat16 g_ksh[BATCH * NKV * EMBED], g_ksl[BATCH * NKV * EMBED];
__device__ __nv_bfloat16 g_vth[BATCH * NH * HD * NKV], g_vtl[BATCH * NH * HD * NKV];
__device__ __nv_bfloat16 g_aoh[BATCH * NQV * EMBED], g_aol[BATCH * NQV * EMBED];
// weight splits
__device__ __nv_bfloat16 g_wqh[EMBED * EMBED], g_wql[EMBED * EMBED];
__device__ __nv_bfloat16 g_wkh[EMBED * EMBED], g_wkl[EMBED * EMBED];
__device__ __nv_bfloat16 g_wvh[EMBED * EMBED], g_wvl[EMBED * EMBED];
__device__ __nv_bfloat16 g_woh[EMBED * EMBED], g_wol[EMBED * EMBED];

// ---------------------------------------------------------------------------
// PTX helpers (sm_80-compatible ISA: compute_103 has no 'a' features)
// ---------------------------------------------------------------------------
__device__ __forceinline__ uint32_t smem_u32(const void* p) {
    uint32_t a;
    asm("{ .reg .u64 t; cvta.to.shared.u64 t, %1; cvt.u32.u64 %0, t; }"
        : "=r"(a) : "l"(p));
    return a;
}
__device__ __forceinline__ void cp16(uint32_t dst, const void* src) {
    asm volatile("cp.async.cg.shared.global [%0], [%1], 16;"
                 :: "r"(dst), "l"(src) : "memory");
}
#define CP_COMMIT() asm volatile("cp.async.commit_group;" ::: "memory")
#define CP_WAIT(n)  asm volatile("cp.async.wait_group %0;" :: "n"(n) : "memory")

__device__ __forceinline__ void ldsm4(uint32_t* r, uint32_t addr) {
    asm volatile("ldmatrix.sync.aligned.m8n8.x4.shared.b16 {%0,%1,%2,%3}, [%4];"
                 : "=r"(r[0]), "=r"(r[1]), "=r"(r[2]), "=r"(r[3]) : "r"(addr));
}
__device__ __forceinline__ void mma16816(float* c, const uint32_t* a,
                                         uint32_t b0, uint32_t b1) {
    asm volatile(
        "mma.sync.aligned.m16n8k16.row.col.f32.bf16.bf16.f32 "
        "{%0,%1,%2,%3}, {%4,%5,%6,%7}, {%8,%9}, {%0,%1,%2,%3};"
        : "+f"(c[0]), "+f"(c[1]), "+f"(c[2]), "+f"(c[3])
        : "r"(a[0]), "r"(a[1]), "r"(a[2]), "r"(a[3]), "r"(b0), "r"(b1));
}
__device__ __forceinline__ uint32_t packbf(float lo, float hi) {
    uint32_t d;
    asm("cvt.rn.bf16x2.f32 %0, %1, %2;" : "=r"(d) : "f"(hi), "f"(lo));
    return d;
}

// ---------------------------------------------------------------------------
// fp32 -> bf16 hi/lo split
// ---------------------------------------------------------------------------
__global__ __launch_bounds__(256) void cvt_split(
    const float* __restrict__ x, __nv_bfloat16* __restrict__ hi,
    __nv_bfloat16* __restrict__ lo)
{
    int i = (blockIdx.x * 256 + threadIdx.x) * 4;
    float4 v = *(const float4*)(x + i);
    __nv_bfloat16 h0 = __float2bfloat16(v.x);
    __nv_bfloat16 h1 = __float2bfloat16(v.y);
    __nv_bfloat16 h2 = __float2bfloat16(v.z);
    __nv_bfloat16 h3 = __float2bfloat16(v.w);
    *(__nv_bfloat162*)(hi + i)     = __nv_bfloat162(h0, h1);
    *(__nv_bfloat162*)(hi + i + 2) = __nv_bfloat162(h2, h3);
    *(__nv_bfloat162*)(lo + i) =
        __nv_bfloat162(__float2bfloat16(v.x - __bfloat162float(h0)),
                       __float2bfloat16(v.y - __bfloat162float(h1)));
    *(__nv_bfloat162*)(lo + i + 2) =
        __nv_bfloat162(__float2bfloat16(v.z - __bfloat162float(h2)),
                       __float2bfloat16(v.w - __bfloat162float(h3)));
}

__global__ __launch_bounds__(256) void log_mult(const float* __restrict__ m,
                                                float* __restrict__ lb) {
    int i = blockIdx.x * 256 + threadIdx.x;
    lb[i] = __logf(m[i]);
}

// V fp32 [b][key][embed] -> transposed bf16 hi/lo [b][h][d][key]
__global__ void transpose_split_v(const float* __restrict__ V,
                                  __nv_bfloat16* __restrict__ vth,
                                  __nv_bfloat16* __restrict__ vtl)
{
    __shared__ float t[32][33];
    const int x = threadIdx.x, y = threadIdx.y;
    const int key0 = blockIdx.x * 32, e0 = blockIdx.y * 32, b = blockIdx.z;
#pragma unroll
    for (int i = 0; i < 4; i++)
        t[y + i * 8][x] = V[((size_t)(b * NKV + key0 + y + i * 8)) * EMBED + e0 + x];
    __syncthreads();
#pragma unroll
    for (int i = 0; i < 4; i++) {
        const int e = e0 + y + i * 8;
        const size_t o = ((size_t)((b * NH + (e >> 6)) * HD + (e & 63))) * NKV + key0 + x;
        float v = t[x][y + i * 8];
        __nv_bfloat16 h = __float2bfloat16(v);
        vth[o] = h;
        vtl[o] = __float2bfloat16(v - __bfloat162float(h));
    }
}

// ---------------------------------------------------------------------------
// HMMA GEMM: C[M,N] = (Ah+Al)[M,K] @ (Bh+Bl)[N,K]^T + bias[N]
// Block 128x256, 8 warps (64x64 warp tile), k-tile 32, 2 stages, 1 bar/iter.
// MODE 0: fp32 out; MODE 1: bf16 hi/lo out; MODE 2: bf16 hi/lo out, x0.125
// ---------------------------------------------------------------------------
#define ROWB   80
#define A_MATB (128 * ROWB)                 // 10240
#define B_MATB (256 * ROWB)                 // 20480
#define STG    (2 * A_MATB + 2 * B_MATB)    // 61440
#define GSMEM  (2 * STG)                    // 122880

template<int MODE>
__global__ __launch_bounds__(256) void gemm_hmma(
    const __nv_bfloat16* __restrict__ Ah, const __nv_bfloat16* __restrict__ Al,
    const __nv_bfloat16* __restrict__ Bh, const __nv_bfloat16* __restrict__ Bl,
    const float* __restrict__ bias, float* __restrict__ C,
    __nv_bfloat16* __restrict__ Oh, __nv_bfloat16* __restrict__ Ol,
    int M, int N, int K)
{
    extern __shared__ __align__(1024) char sm[];
    const uint32_t sb = smem_u32(sm);
    const int tid = threadIdx.x;
    const int lane = tid & 31, wid = tid >> 5;
    const int warp_m = wid >> 2, warp_n = wid & 3;      // 2 x 4 warps
    const int bm = blockIdx.y * 128, bn = blockIdx.x * 256;

    const int lrw = tid >> 1;
    const int lck = (tid & 1) * 2;   // chunk pair (16B each)
    const __nv_bfloat16* gAh = Ah + (size_t)(bm + lrw) * K + lck * 8;
    const __nv_bfloat16* gAl = Al + (size_t)(bm + lrw) * K + lck * 8;
    const __nv_bfloat16* gBh0 = Bh + (size_t)(bn + lrw) * K + lck * 8;
    const __nv_bfloat16* gBl0 = Bl + (size_t)(bn + lrw) * K + lck * 8;
    const __nv_bfloat16* gBh1 = gBh0 + (size_t)128 * K;
    const __nv_bfloat16* gBl1 = gBl0 + (size_t)128 * K;
    const uint32_t dA  = lrw * ROWB + lck * 16;
    const uint32_t dB0 = 2 * A_MATB + lrw * ROWB + lck * 16;
    const uint32_t dB1 = dB0 + 128 * ROWB;

    const int NKT = K / 32;

#define ISSUE(s, kt) do {                                                   \
        const uint32_t so = sb + (s) * STG;                                 \
        const size_t go = (size_t)(kt) * 32;                                \
        cp16(so + dA,                   gAh + go);                          \
        cp16(so + dA + 16,              gAh + go + 8);                      \
        cp16(so + dA + A_MATB,          gAl + go);                          \
        cp16(so + dA + A_MATB + 16,     gAl + go + 8);                      \
        cp16(so + dB0,                  gBh0 + go);                         \
        cp16(so + dB0 + 16,             gBh0 + go + 8);                     \
        cp16(so + dB0 + B_MATB,         gBl0 + go);                         \
        cp16(so + dB0 + B_MATB + 16,    gBl0 + go + 8);                     \
        cp16(so + dB1,                  gBh1 + go);                         \
        cp16(so + dB1 + 16,             gBh1 + go + 8);                     \
        cp16(so + dB1 + B_MATB,         gBl1 + go);                         \
        cp16(so + dB1 + B_MATB + 16,    gBl1 + go + 8);                     \
        CP_COMMIT();                                                       \
    } while (0)

    ISSUE(0, 0);

    float c[4][8][4];
#pragma unroll
    for (int i = 0; i < 4; i++)
#pragma unroll
        for (int j = 0; j < 8; j++)
#pragma unroll
            for (int q = 0; q < 4; q++) c[i][j][q] = 0.f;

    const uint32_t frow = lane & 15;
    const uint32_t fkb  = ((lane >> 4) & 1) * 16;
    const uint32_t aBase = (warp_m * 64 + frow) * ROWB + fkb;
    const uint32_t bBase = 2 * A_MATB + (warp_n * 64 + frow) * ROWB + fkb;

#pragma unroll 1
    for (int kt = 0; kt < NKT; kt++) {
        CP_WAIT(0);
        __syncthreads();
        if (kt + 1 < NKT) ISSUE((kt + 1) & 1, kt + 1);
        const uint32_t st = sb + (kt & 1) * STG;

#pragma unroll
        for (int ks = 0; ks < 2; ks++) {
            const uint32_t ko = ks * 32;
            uint32_t ah[4][4], al_[4][4];
#pragma unroll
            for (int mi = 0; mi < 4; mi++) {
                ldsm4(ah[mi],  st + aBase + mi * 16 * ROWB + ko);
                ldsm4(al_[mi], st + A_MATB + aBase + mi * 16 * ROWB + ko);
            }
#pragma unroll
            for (int nb = 0; nb < 4; nb++) {
                uint32_t bh[4], bl[4];
                const uint32_t ba = st + bBase + nb * 16 * ROWB + ko;
                ldsm4(bh, ba);
                ldsm4(bl, ba + B_MATB);
#pragma unroll
                for (int mi = 0; mi < 4; mi++) {
                    mma16816(c[mi][nb * 2],     ah[mi],  bh[0], bh[2]);
                    mma16816(c[mi][nb * 2],     ah[mi],  bl[0], bl[2]);
                    mma16816(c[mi][nb * 2],     al_[mi], bh[0], bh[2]);
                    mma16816(c[mi][nb * 2 + 1], ah[mi],  bh[1], bh[3]);
                    mma16816(c[mi][nb * 2 + 1], ah[mi],  bl[1], bl[3]);
                    mma16816(c[mi][nb * 2 + 1], al_[mi], bh[1], bh[3]);
                }
            }
        }
    }

    const int erow = lane >> 2, ecol = (lane & 3) * 2;
#pragma unroll
    for (int mi = 0; mi < 4; mi++) {
        const int r0 = bm + warp_m * 64 + mi * 16 + erow;
#pragma unroll
        for (int n8 = 0; n8 < 8; n8++) {
            const int cc = bn + warp_n * 64 + n8 * 8 + ecol;
            const float b0 = bias[cc], b1 = bias[cc + 1];
            if (MODE == 0) {
                float2 v0 = {c[mi][n8][0] + b0, c[mi][n8][1] + b1};
                float2 v1 = {c[mi][n8][2] + b0, c[mi][n8][3] + b1};
                *(float2*)(C + (size_t)r0 * N + cc)       = v0;
                *(float2*)(C + (size_t)(r0 + 8) * N + cc) = v1;
            } else {
                const float sc = (MODE == 2) ? 0.125f : 1.0f;
                float x0 = (c[mi][n8][0] + b0) * sc, x1 = (c[mi][n8][1] + b1) * sc;
                float x2 = (c[mi][n8][2] + b0) * sc, x3 = (c[mi][n8][3] + b1) * sc;
                float h0 = __bfloat162float(__float2bfloat16(x0));
                float h1 = __bfloat162float(__float2bfloat16(x1));
                float h2 = __bfloat162float(__float2bfloat16(x2));
                float h3 = __bfloat162float(__float2bfloat16(x3));
                size_t i0 = (size_t)r0 * N + cc, i1 = (size_t)(r0 + 8) * N + cc;
                *(uint32_t*)(Oh + i0) = packbf(h0, h1);
                *(uint32_t*)(Oh + i1) = packbf(h2, h3);
                *(uint32_t*)(Ol + i0) = packbf(x0 - h0, x1 - h1);
                *(uint32_t*)(Ol + i1) = packbf(x2 - h2, x3 - h3);
            }
        }
    }
#undef ISSUE
}

// ---------------------------------------------------------------------------
// HMMA flash attention, bf16 split: softmax(QK^T/8 + log m) V
// Q comes pre-scaled/pre-split from the Q-projection epilogue.
// ---------------------------------------------------------------------------
#define QROW 144
#define SQ_L   (128 * QROW)
#define SQ_SZ  (2 * 128 * QROW)
#define SK_L   (64 * QROW)
#define SVT_H  (2 * 64 * QROW)
#define SVT_L  (3 * 64 * QROW)
#define SLB    (4 * 64 * QROW)
#define STG_SZ (4 * 64 * QROW + 256)
#define ASMEM  (SQ_SZ + 2 * STG_SZ)

__global__ __launch_bounds__(256) void attn_hmma(
    const __nv_bfloat16* __restrict__ Qh, const __nv_bfloat16* __restrict__ Ql,
    const __nv_bfloat16* __restrict__ Kh, const __nv_bfloat16* __restrict__ Kl,
    const __nv_bfloat16* __restrict__ VTh, const __nv_bfloat16* __restrict__ VTl,
    const float* __restrict__ lbG,
    __nv_bfloat16* __restrict__ Oh, __nv_bfloat16* __restrict__ Ol)
{
    extern __shared__ __align__(1024) char sm[];
    const uint32_t sb = smem_u32(sm);
    const int qt = blockIdx.x, h = blockIdx.y, b = blockIdx.z;
    const int tid = threadIdx.x;
    const int lane = tid & 31, wid = tid >> 5;

    // ---- Q tile via cp.async (already scaled & split) ----
    {
        const int row = tid >> 1;
        const int co = (tid & 1) * 32;   // element offset within 64
        const __nv_bfloat16* gqh = Qh + ((size_t)(b * NQV + qt * 128 + row)) * EMBED + h * HD + co;
        const __nv_bfloat16* gql = Ql + ((size_t)(b * NQV + qt * 128 + row)) * EMBED + h * HD + co;
        const uint32_t dh = sb + row * QROW + co * 2;
        const uint32_t dl = sb + SQ_L + row * QROW + co * 2;
#pragma unroll
        for (int i = 0; i < 4; i++) {
            cp16(dh + i * 16, gqh + i * 8);
            cp16(dl + i * 16, gql + i * 8);
        }
    }

    // ---- stage loader ----
    const int srow = tid >> 2, scq = tid & 3;
    const __nv_bfloat16* gK_h = Kh + ((size_t)(b * NKV + srow)) * EMBED + h * HD + scq * 16;
    const __nv_bfloat16* gK_l = Kl + ((size_t)(b * NKV + srow)) * EMBED + h * HD + scq * 16;
    const __nv_bfloat16* gV_h = VTh + ((size_t)((b * NH + h) * HD + srow)) * NKV + scq * 16;
    const __nv_bfloat16* gV_l = VTl + ((size_t)((b * NH + h) * HD + srow)) * NKV + scq * 16;
    const uint32_t sdst = srow * QROW + scq * 32;
    const float* gLB = lbG + (size_t)b * NKV;

#define AISSUE(s, kt) do {                                                  \
        const uint32_t so = sb + SQ_SZ + (s) * STG_SZ;                      \
        const size_t koK = (size_t)(kt) * 64 * EMBED;                       \
        const size_t koV = (size_t)(kt) * 64;                               \
        cp16(so + sdst,              gK_h + koK);                           \
        cp16(so + sdst + 16,         gK_h + koK + 8);                       \
        cp16(so + SK_L + sdst,       gK_l + koK);                           \
        cp16(so + SK_L + sdst + 16,  gK_l + koK + 8);                       \
        cp16(so + SVT_H + sdst,      gV_h + koV);                           \
        cp16(so + SVT_H + sdst + 16, gV_h + koV + 8);                       \
        cp16(so + SVT_L + sdst,      gV_l + koV);                           \
        cp16(so + SVT_L + sdst + 16, gV_l + koV + 8);                       \
        if (tid < 16) cp16(so + SLB + tid * 16, gLB + (kt) * 64 + tid * 4); \
        CP_COMMIT();                                                       \
    } while (0)

    AISSUE(0, 0);   // Q loads join this commit group

    const uint32_t frow = lane & 15;
    const uint32_t fkb  = ((lane >> 4) & 1) * 16;
    const uint32_t qBase = (wid * 16 + frow) * QROW + fkb;
    uint32_t qh[4][4];

    float o[8][4];
#pragma unroll
    for (int j = 0; j < 8; j++)
#pragma unroll
        for (int q = 0; q < 4; q++) o[j][q] = 0.f;
    float m0 = -1e30f, m1 = -1e30f, l0 = 0.f, l1 = 0.f;

    const int NT = NKV / 64;
#pragma unroll 1
    for (int kt = 0; kt < NT; kt++) {
        CP_WAIT(0);
        __syncthreads();
        if (kt == 0) {
#pragma unroll
            for (int ks = 0; ks < 4; ks++) ldsm4(qh[ks], sb + qBase + ks * 32);
        }
        if (kt + 1 < NT) AISSUE((kt + 1) & 1, kt + 1);
        const uint32_t st = sb + SQ_SZ + (kt & 1) * STG_SZ;

        // ---- S = Q K^T ----
        float c[8][4];
#pragma unroll
        for (int j = 0; j < 8; j++)
#pragma unroll
            for (int q = 0; q < 4; q++) c[j][q] = 0.f;

#pragma unroll
        for (int ks = 0; ks < 4; ks++) {
            uint32_t ql_[4];
            ldsm4(ql_, sb + SQ_L + qBase + ks * 32);
#pragma unroll
            for (int nb = 0; nb < 4; nb++) {
                uint32_t kh[4], kl[4];
                const uint32_t ka = st + (nb * 16 + frow) * QROW + fkb + ks * 32;
                ldsm4(kh, ka);
                ldsm4(kl, ka + SK_L);
                mma16816(c[nb * 2], qh[ks], kh[0], kh[2]);
                mma16816(c[nb * 2], qh[ks], kl[0], kl[2]);
                mma16816(c[nb * 2], ql_,    kh[0], kh[2]);
                mma16816(c[nb * 2 + 1], qh[ks], kh[1], kh[3]);
                mma16816(c[nb * 2 + 1], qh[ks], kl[1], kl[3]);
                mma16816(c[nb * 2 + 1], ql_,    kh[1], kh[3]);
            }
        }

        // ---- + log multiplicity ----
        const float* lbs = (const float*)(sm + SQ_SZ + (kt & 1) * STG_SZ + SLB);
#pragma unroll
        for (int j = 0; j < 8; j++) {
            float2 lb2 = *(const float2*)(lbs + j * 8 + (lane & 3) * 2);
            c[j][0] += lb2.x; c[j][1] += lb2.y;
            c[j][2] += lb2.x; c[j][3] += lb2.y;
        }

        // ---- online softmax ----
        float rm0 = -1e30f, rm1 = -1e30f;
#pragma unroll
        for (int j = 0; j < 8; j++) {
            rm0 = fmaxf(rm0, fmaxf(c[j][0], c[j][1]));
            rm1 = fmaxf(rm1, fmaxf(c[j][2], c[j][3]));
        }
#pragma unroll
        for (int off = 1; off < 4; off <<= 1) {
            rm0 = fmaxf(rm0, __shfl_xor_sync(0xffffffffu, rm0, off));
            rm1 = fmaxf(rm1, __shfl_xor_sync(0xffffffffu, rm1, off));
        }
        const float mn0 = fmaxf(m0, rm0), mn1 = fmaxf(m1, rm1);
        const float al0 = __expf(m0 - mn0), al1 = __expf(m1 - mn1);
        float rs0 = 0.f, rs1 = 0.f;
#pragma unroll
        for (int j = 0; j < 8; j++) {
            c[j][0] = __expf(c[j][0] - mn0); rs0 += c[j][0];
            c[j][1] = __expf(c[j][1] - mn0); rs0 += c[j][1];
            c[j][2] = __expf(c[j][2] - mn1); rs1 += c[j][2];
            c[j][3] = __expf(c[j][3] - mn1); rs1 += c[j][3];
        }
#pragma unroll
        for (int off = 1; off < 4; off <<= 1) {
            rs0 += __shfl_xor_sync(0xffffffffu, rs0, off);
            rs1 += __shfl_xor_sync(0xffffffffu, rs1, off);
        }
        l0 = l0 * al0 + rs0;  m0 = mn0;
        l1 = l1 * al1 + rs1;  m1 = mn1;
#pragma unroll
        for (int j = 0; j < 8; j++) {
            o[j][0] *= al0; o[j][1] *= al0;
            o[j][2] *= al1; o[j][3] *= al1;
        }

        // ---- O += P V ----
#pragma unroll
        for (int kk = 0; kk < 4; kk++) {
            const int j0 = 2 * kk, j1 = 2 * kk + 1;
            float ph[8], pl[8];
            const float pv[8] = {c[j0][0], c[j0][1], c[j0][2], c[j0][3],
                                 c[j1][0], c[j1][1], c[j1][2], c[j1][3]};
#pragma unroll
            for (int q = 0; q < 8; q++) {
                ph[q] = __bfloat162float(__float2bfloat16(pv[q]));
                pl[q] = pv[q] - ph[q];
            }
            uint32_t ah[4], al_[4];
            ah[0] = packbf(ph[0], ph[1]);  ah[1] = packbf(ph[2], ph[3]);
            ah[2] = packbf(ph[4], ph[5]);  ah[3] = packbf(ph[6], ph[7]);
            al_[0] = packbf(pl[0], pl[1]); al_[1] = packbf(pl[2], pl[3]);
            al_[2] = packbf(pl[4], pl[5]); al_[3] = packbf(pl[6], pl[7]);
#pragma unroll
            for (int nb = 0; nb < 4; nb++) {
                uint32_t vh[4], vl[4];
                const uint32_t va = st + SVT_H + (nb * 16 + frow) * QROW + fkb + kk * 32;
                ldsm4(vh, va);
                ldsm4(vl, va + (SVT_L - SVT_H));
                mma16816(o[nb * 2], ah,  vh[0], vh[2]);
                mma16816(o[nb * 2], al_, vh[0], vh[2]);
                mma16816(o[nb * 2], ah,  vl[0], vl[2]);
                mma16816(o[nb * 2 + 1], ah,  vh[1], vh[3]);
                mma16816(o[nb * 2 + 1], al_, vh[1], vh[3]);
                mma16816(o[nb * 2 + 1], ah,  vl[1], vl[3]);
            }
        }
    }

    // ---- epilogue ----
    const float inv0 = 1.f / l0, inv1 = 1.f / l1;
    const int r0 = qt * 128 + wid * 16 + (lane >> 2);
    const int cc0 = h * HD + (lane & 3) * 2;
#pragma unroll
    for (int j = 0; j < 8; j++) {
        const int col = cc0 + j * 8;
        {
            float v0 = o[j][0] * inv0, v1 = o[j][1] * inv0;
            float h0 = __bfloat162float(__float2bfloat16(v0));
            float h1 = __bfloat162float(__float2bfloat16(v1));
            size_t idx = ((size_t)(b * NQV + r0)) * EMBED + col;
            *(uint32_t*)(Oh + idx) = packbf(h0, h1);
            *(uint32_t*)(Ol + idx) = packbf(v0 - h0, v1 - h1);
        }
        {
            float v0 = o[j][2] * inv1, v1 = o[j][3] * inv1;
            float h0 = __bfloat162float(__float2bfloat16(v0));
            float h1 = __bfloat162float(__float2bfloat16(v1));
            size_t idx = ((size_t)(b * NQV + r0 + 8)) * EMBED + col;
            *(uint32_t*)(Oh + idx) = packbf(h0, h1);
            *(uint32_t*)(Ol + idx) = packbf(v0 - h0, v1 - h1);
        }
    }
#undef AISSUE
}

// ---------------------------------------------------------------------------
extern "C" void kernel_launch(void* const* d_in, const int* in_sizes, int n_in,
                              void* d_out, int out_size)
{
    const float* query = (const float*)d_in[0];
    const float* key   = (const float*)d_in[1];
    const float* value = (const float*)d_in[2];
    const float* mult  = (const float*)d_in[3];
    const float* wq_w  = (const float*)d_in[4];
    const float* wq_b  = (const float*)d_in[5];
    const float* wk_w  = (const float*)d_in[6];
    const float* wk_b  = (const float*)d_in[7];
    const float* wv_w  = (const float*)d_in[8];
    const float* wv_b  = (const float*)d_in[9];
    const float* wo_w  = (const float*)d_in[10];
    const float* wo_b  = (const float*)d_in[11];
    float* out = (float*)d_out;

    float *gv, *glb;
    cudaGetSymbolAddress((void**)&gv, g_V);
    cudaGetSymbolAddress((void**)&glb, g_lb);
    __nv_bfloat16 *qh,*ql,*kh,*kl,*vh,*vl;
    __nv_bfloat16 *qsh,*qsl,*ksh,*ksl,*vth,*vtl,*aoh,*aol;
    __nv_bfloat16 *wqh,*wql,*wkh,*wkl,*wvh,*wvl,*woh,*wol;
    cudaGetSymbolAddress((void**)&qh, g_qh);   cudaGetSymbolAddress((void**)&ql, g_ql);
    cudaGetSymbolAddress((void**)&kh, g_kh);   cudaGetSymbolAddress((void**)&kl, g_kl);
    cudaGetSymbolAddress((void**)&vh, g_vh);   cudaGetSymbolAddress((void**)&vl, g_vl);
    cudaGetSymbolAddress((void**)&qsh, g_qsh); cudaGetSymbolAddress((void**)&qsl, g_qsl);
    cudaGetSymbolAddress((void**)&ksh, g_ksh); cudaGetSymbolAddress((void**)&ksl, g_ksl);
    cudaGetSymbolAddress((void**)&vth, g_vth); cudaGetSymbolAddress((void**)&vtl, g_vtl);
    cudaGetSymbolAddress((void**)&aoh, g_aoh); cudaGetSymbolAddress((void**)&aol, g_aol);
    cudaGetSymbolAddress((void**)&wqh, g_wqh); cudaGetSymbolAddress((void**)&wql, g_wql);
    cudaGetSymbolAddress((void**)&wkh, g_wkh); cudaGetSymbolAddress((void**)&wkl, g_wkl);
    cudaGetSymbolAddress((void**)&wvh, g_wvh); cudaGetSymbolAddress((void**)&wvl, g_wvl);
    cudaGetSymbolAddress((void**)&woh, g_woh); cudaGetSymbolAddress((void**)&wol, g_wol);

    cudaFuncSetAttribute(gemm_hmma<0>, cudaFuncAttributeMaxDynamicSharedMemorySize, GSMEM);
    cudaFuncSetAttribute(gemm_hmma<1>, cudaFuncAttributeMaxDynamicSharedMemorySize, GSMEM);
    cudaFuncSetAttribute(gemm_hmma<2>, cudaFuncAttributeMaxDynamicSharedMemorySize, GSMEM);
    cudaFuncSetAttribute(attn_hmma, cudaFuncAttributeMaxDynamicSharedMemorySize, ASMEM);

    const int MQ = BATCH * NQV;
    const int MK = BATCH * NKV;
    const int NW = EMBED * EMBED;

    cvt_split<<<MQ * EMBED / 1024, 256>>>(query, qh, ql);
    cvt_split<<<MK * EMBED / 1024, 256>>>(key,   kh, kl);
    cvt_split<<<MK * EMBED / 1024, 256>>>(value, vh, vl);
    cvt_split<<<NW / 1024, 256>>>(wq_w, wqh, wql);
    cvt_split<<<NW / 1024, 256>>>(wk_w, wkh, wkl);
    cvt_split<<<NW / 1024, 256>>>(wv_w, wvh, wvl);
    cvt_split<<<NW / 1024, 256>>>(wo_w, woh, wol);
    log_mult<<<MK / 256, 256>>>(mult, glb);

    // projections: Q -> scaled split, K -> split, V -> fp32 (for transpose)
    gemm_hmma<2><<<dim3(EMBED / 256, MQ / 128), 256, GSMEM>>>(
        qh, ql, wqh, wql, wq_b, nullptr, qsh, qsl, MQ, EMBED, EMBED);
    gemm_hmma<1><<<dim3(EMBED / 256, MK / 128), 256, GSMEM>>>(
        kh, kl, wkh, wkl, wk_b, nullptr, ksh, ksl, MK, EMBED, EMBED);
    gemm_hmma<0><<<dim3(EMBED / 256, MK / 128), 256, GSMEM>>>(
        vh, vl, wvh, wvl, wv_b, gv, nullptr, nullptr, MK, EMBED, EMBED);

    transpose_split_v<<<dim3(NKV / 32, EMBED / 32, BATCH), dim3(32, 8)>>>(gv, vth, vtl);

    attn_hmma<<<dim3(NQV / 128, NH, BATCH), 256, ASMEM>>>(
        qsh, qsl, ksh, ksl, vth, vtl, glb, aoh, aol);

    gemm_hmma<0><<<dim3(EMBED / 256, MQ / 128), 256, GSMEM>>>(
        aoh, aol, woh, wol, wo_b, out, nullptr, nullptr, MQ, EMBED, EMBED);
}

// round 6
// speedup vs baseline: 2.8836x; 1.1215x over previous
#include <cuda_runtime.h>
#include <cuda_bf16.h>
#include <cuda_fp16.h>
#include <math.h>
#include <stdint.h>

#define EMBED 1024
#define NQV   1024
#define NKV   2048
#define BATCH 4
#define NH    16
#define HD    64

// ---------------------------------------------------------------------------
// Scratch (__device__ globals — allocation-free rule)
// ---------------------------------------------------------------------------
__device__ float g_lb[BATCH * NKV];

// bf16 path (logit chain)
__device__ __nv_bfloat16 g_qh[BATCH * NQV * EMBED], g_ql[BATCH * NQV * EMBED];
__device__ __nv_bfloat16 g_kh[BATCH * NKV * EMBED], g_kl[BATCH * NKV * EMBED];
__device__ __nv_bfloat16 g_qsh[BATCH * NQV * EMBED], g_qsl[BATCH * NQV * EMBED];
__device__ __nv_bfloat16 g_ksh[BATCH * NKV * EMBED], g_ksl[BATCH * NKV * EMBED];
__device__ __nv_bfloat16 g_wqh[EMBED * EMBED], g_wql[EMBED * EMBED];
__device__ __nv_bfloat16 g_wkh[EMBED * EMBED], g_wkl[EMBED * EMBED];

// fp16 path (post-softmax linear chain)
__device__ __half g_vh16[BATCH * NKV * EMBED], g_vl16[BATCH * NKV * EMBED];
__device__ __half g_wvh16[EMBED * EMBED];
__device__ __half g_woh16[EMBED * EMBED];
__device__ __half g_vth16[BATCH * NH * HD * NKV];
__device__ __half g_aoh16[BATCH * NQV * EMBED], g_aol16[BATCH * NQV * EMBED];

// ---------------------------------------------------------------------------
// PTX helpers (sm_80-compatible ISA: compute_103 has no 'a' features)
// ---------------------------------------------------------------------------
__device__ __forceinline__ uint32_t smem_u32(const void* p) {
    uint32_t a;
    asm("{ .reg .u64 t; cvta.to.shared.u64 t, %1; cvt.u32.u64 %0, t; }"
        : "=r"(a) : "l"(p));
    return a;
}
__device__ __forceinline__ void cp16(uint32_t dst, const void* src) {
    asm volatile("cp.async.cg.shared.global [%0], [%1], 16;"
                 :: "r"(dst), "l"(src) : "memory");
}
#define CP_COMMIT() asm volatile("cp.async.commit_group;" ::: "memory")
#define CP_WAIT(n)  asm volatile("cp.async.wait_group %0;" :: "n"(n) : "memory")

__device__ __forceinline__ void ldsm4(uint32_t* r, uint32_t addr) {
    asm volatile("ldmatrix.sync.aligned.m8n8.x4.shared.b16 {%0,%1,%2,%3}, [%4];"
                 : "=r"(r[0]), "=r"(r[1]), "=r"(r[2]), "=r"(r[3]) : "r"(addr));
}
__device__ __forceinline__ void mma_bf(float* c, const uint32_t* a,
                                       uint32_t b0, uint32_t b1) {
    asm volatile(
        "mma.sync.aligned.m16n8k16.row.col.f32.bf16.bf16.f32 "
        "{%0,%1,%2,%3}, {%4,%5,%6,%7}, {%8,%9}, {%0,%1,%2,%3};"
        : "+f"(c[0]), "+f"(c[1]), "+f"(c[2]), "+f"(c[3])
        : "r"(a[0]), "r"(a[1]), "r"(a[2]), "r"(a[3]), "r"(b0), "r"(b1));
}
__device__ __forceinline__ void mma_h(float* c, const uint32_t* a,
                                      uint32_t b0, uint32_t b1) {
    asm volatile(
        "mma.sync.aligned.m16n8k16.row.col.f32.f16.f16.f32 "
        "{%0,%1,%2,%3}, {%4,%5,%6,%7}, {%8,%9}, {%0,%1,%2,%3};"
        : "+f"(c[0]), "+f"(c[1]), "+f"(c[2]), "+f"(c[3])
        : "r"(a[0]), "r"(a[1]), "r"(a[2]), "r"(a[3]), "r"(b0), "r"(b1));
}
__device__ __forceinline__ uint32_t packbf(float lo, float hi) {
    uint32_t d;
    asm("cvt.rn.bf16x2.f32 %0, %1, %2;" : "=r"(d) : "f"(hi), "f"(lo));
    return d;
}
__device__ __forceinline__ uint32_t packh(float lo, float hi) {
    __half2 v = __floats2half2_rn(lo, hi);
    return *(uint32_t*)&v;
}

// ---------------------------------------------------------------------------
// conversion kernels
// ---------------------------------------------------------------------------
__global__ __launch_bounds__(256) void cvt_split(
    const float* __restrict__ x, __nv_bfloat16* __restrict__ hi,
    __nv_bfloat16* __restrict__ lo)
{
    int i = (blockIdx.x * 256 + threadIdx.x) * 4;
    float4 v = *(const float4*)(x + i);
    __nv_bfloat16 h0 = __float2bfloat16(v.x), h1 = __float2bfloat16(v.y);
    __nv_bfloat16 h2 = __float2bfloat16(v.z), h3 = __float2bfloat16(v.w);
    *(__nv_bfloat162*)(hi + i)     = __nv_bfloat162(h0, h1);
    *(__nv_bfloat162*)(hi + i + 2) = __nv_bfloat162(h2, h3);
    *(__nv_bfloat162*)(lo + i) =
        __nv_bfloat162(__float2bfloat16(v.x - __bfloat162float(h0)),
                       __float2bfloat16(v.y - __bfloat162float(h1)));
    *(__nv_bfloat162*)(lo + i + 2) =
        __nv_bfloat162(__float2bfloat16(v.z - __bfloat162float(h2)),
                       __float2bfloat16(v.w - __bfloat162float(h3)));
}

__global__ __launch_bounds__(256) void cvt_split_h(
    const float* __restrict__ x, __half* __restrict__ hi, __half* __restrict__ lo)
{
    int i = (blockIdx.x * 256 + threadIdx.x) * 4;
    float4 v = *(const float4*)(x + i);
    __half h0 = __float2half_rn(v.x), h1 = __float2half_rn(v.y);
    __half h2 = __float2half_rn(v.z), h3 = __float2half_rn(v.w);
    *(__half2*)(hi + i)     = __half2(h0, h1);
    *(__half2*)(hi + i + 2) = __half2(h2, h3);
    *(__half2*)(lo + i) = __half2(__float2half_rn(v.x - __half2float(h0)),
                                  __float2half_rn(v.y - __half2float(h1)));
    *(__half2*)(lo + i + 2) = __half2(__float2half_rn(v.z - __half2float(h2)),
                                      __float2half_rn(v.w - __half2float(h3)));
}

__global__ __launch_bounds__(256) void cvt_h(
    const float* __restrict__ x, __half* __restrict__ hi)
{
    int i = (blockIdx.x * 256 + threadIdx.x) * 4;
    float4 v = *(const float4*)(x + i);
    *(__half2*)(hi + i)     = __floats2half2_rn(v.x, v.y);
    *(__half2*)(hi + i + 2) = __floats2half2_rn(v.z, v.w);
}

__global__ __launch_bounds__(256) void log_mult(const float* __restrict__ m,
                                                float* __restrict__ lb) {
    int i = blockIdx.x * 256 + threadIdx.x;
    lb[i] = __logf(m[i]);
}

// ---------------------------------------------------------------------------
// bf16 3-term HMMA GEMM (logit chain): C = (Ah+Al)(Bh+Bl)^T + bias
// Block 128x256, 8 warps 64x64, k-tile 32, 3 stages.
// MODE 1: bf16 hi/lo out; MODE 2: bf16 hi/lo out scaled 0.125
// ---------------------------------------------------------------------------
#define ROWB   80
#define A_MATB (128 * ROWB)
#define B_MATB (256 * ROWB)
#define STG3   (2 * A_MATB + 2 * B_MATB)    // 61440
#define GSMEM3 (3 * STG3)                   // 184320

template<int MODE>
__global__ __launch_bounds__(256) void gemm_bf3(
    const __nv_bfloat16* __restrict__ Ah, const __nv_bfloat16* __restrict__ Al,
    const __nv_bfloat16* __restrict__ Bh, const __nv_bfloat16* __restrict__ Bl,
    const float* __restrict__ bias,
    __nv_bfloat16* __restrict__ Oh, __nv_bfloat16* __restrict__ Ol,
    int M, int N, int K)
{
    extern __shared__ __align__(1024) char sm[];
    const uint32_t sb = smem_u32(sm);
    const int tid = threadIdx.x;
    const int lane = tid & 31, wid = tid >> 5;
    const int warp_m = wid >> 2, warp_n = wid & 3;
    const int bm = blockIdx.y * 128, bn = blockIdx.x * 256;

    const int lrw = tid >> 1;
    const int lck = (tid & 1) * 2;
    const __nv_bfloat16* gAh = Ah + (size_t)(bm + lrw) * K + lck * 8;
    const __nv_bfloat16* gAl = Al + (size_t)(bm + lrw) * K + lck * 8;
    const __nv_bfloat16* gBh0 = Bh + (size_t)(bn + lrw) * K + lck * 8;
    const __nv_bfloat16* gBl0 = Bl + (size_t)(bn + lrw) * K + lck * 8;
    const __nv_bfloat16* gBh1 = gBh0 + (size_t)128 * K;
    const __nv_bfloat16* gBl1 = gBl0 + (size_t)128 * K;
    const uint32_t dA  = lrw * ROWB + lck * 16;
    const uint32_t dB0 = 2 * A_MATB + lrw * ROWB + lck * 16;
    const uint32_t dB1 = dB0 + 128 * ROWB;

    const int NKT = K / 32;

#define ISSUE(s, kt) do {                                                   \
        const uint32_t so = sb + (s) * STG3;                                \
        const size_t go = (size_t)(kt) * 32;                                \
        cp16(so + dA,                gAh + go);                             \
        cp16(so + dA + 16,           gAh + go + 8);                         \
        cp16(so + dA + A_MATB,       gAl + go);                             \
        cp16(so + dA + A_MATB + 16,  gAl + go + 8);                         \
        cp16(so + dB0,               gBh0 + go);                            \
        cp16(so + dB0 + 16,          gBh0 + go + 8);                        \
        cp16(so + dB0 + B_MATB,      gBl0 + go);                            \
        cp16(so + dB0 + B_MATB + 16, gBl0 + go + 8);                        \
        cp16(so + dB1,               gBh1 + go);                            \
        cp16(so + dB1 + 16,          gBh1 + go + 8);                        \
        cp16(so + dB1 + B_MATB,      gBl1 + go);                            \
        cp16(so + dB1 + B_MATB + 16, gBl1 + go + 8);                        \
        CP_COMMIT();                                                       \
    } while (0)

    ISSUE(0, 0);
    ISSUE(1, 1);

    float c[4][8][4];
#pragma unroll
    for (int i = 0; i < 4; i++)
#pragma unroll
        for (int j = 0; j < 8; j++)
#pragma unroll
            for (int q = 0; q < 4; q++) c[i][j][q] = 0.f;

    const uint32_t frow = lane & 15;
    const uint32_t fkb  = ((lane >> 4) & 1) * 16;
    const uint32_t aBase = (warp_m * 64 + frow) * ROWB + fkb;
    const uint32_t bBase = 2 * A_MATB + (warp_n * 64 + frow) * ROWB + fkb;

#pragma unroll 1
    for (int kt = 0; kt < NKT; kt++) {
        if (kt + 1 < NKT) { CP_WAIT(1); } else { CP_WAIT(0); }
        __syncthreads();
        if (kt + 2 < NKT) ISSUE((kt + 2) % 3, kt + 2);
        const uint32_t st = sb + (kt % 3) * STG3;

#pragma unroll
        for (int ks = 0; ks < 2; ks++) {
            const uint32_t ko = ks * 32;
            uint32_t ah[4][4], al_[4][4];
#pragma unroll
            for (int mi = 0; mi < 4; mi++) {
                ldsm4(ah[mi],  st + aBase + mi * 16 * ROWB + ko);
                ldsm4(al_[mi], st + A_MATB + aBase + mi * 16 * ROWB + ko);
            }
#pragma unroll
            for (int nb = 0; nb < 4; nb++) {
                uint32_t bh[4], bl[4];
                const uint32_t ba = st + bBase + nb * 16 * ROWB + ko;
                ldsm4(bh, ba);
                ldsm4(bl, ba + B_MATB);
#pragma unroll
                for (int mi = 0; mi < 4; mi++) {
                    mma_bf(c[mi][nb * 2],     ah[mi],  bh[0], bh[2]);
                    mma_bf(c[mi][nb * 2],     ah[mi],  bl[0], bl[2]);
                    mma_bf(c[mi][nb * 2],     al_[mi], bh[0], bh[2]);
                    mma_bf(c[mi][nb * 2 + 1], ah[mi],  bh[1], bh[3]);
                    mma_bf(c[mi][nb * 2 + 1], ah[mi],  bl[1], bl[3]);
                    mma_bf(c[mi][nb * 2 + 1], al_[mi], bh[1], bh[3]);
                }
            }
        }
    }

    const int erow = lane >> 2, ecol = (lane & 3) * 2;
#pragma unroll
    for (int mi = 0; mi < 4; mi++) {
        const int r0 = bm + warp_m * 64 + mi * 16 + erow;
#pragma unroll
        for (int n8 = 0; n8 < 8; n8++) {
            const int cc = bn + warp_n * 64 + n8 * 8 + ecol;
            const float b0 = bias[cc], b1 = bias[cc + 1];
            const float sc = (MODE == 2) ? 0.125f : 1.0f;
            float x0 = (c[mi][n8][0] + b0) * sc, x1 = (c[mi][n8][1] + b1) * sc;
            float x2 = (c[mi][n8][2] + b0) * sc, x3 = (c[mi][n8][3] + b1) * sc;
            float h0 = __bfloat162float(__float2bfloat16(x0));
            float h1 = __bfloat162float(__float2bfloat16(x1));
            float h2 = __bfloat162float(__float2bfloat16(x2));
            float h3 = __bfloat162float(__float2bfloat16(x3));
            size_t i0 = (size_t)r0 * N + cc, i1 = (size_t)(r0 + 8) * N + cc;
            *(uint32_t*)(Oh + i0) = packbf(h0, h1);
            *(uint32_t*)(Oh + i1) = packbf(h2, h3);
            *(uint32_t*)(Ol + i0) = packbf(x0 - h0, x1 - h1);
            *(uint32_t*)(Ol + i1) = packbf(x2 - h2, x3 - h3);
        }
    }
#undef ISSUE
}

// ---------------------------------------------------------------------------
// fp16 2-term HMMA GEMM (linear chain): C = (Ah+Al) Bh^T + bias
// MODE 0: fp32 out; MODE 3: write transposed fp16 V^T [b][h][d][key]
// ---------------------------------------------------------------------------
#define F2_STG  (2 * A_MATB + B_MATB)      // 40960
#define F2_SMEM (3 * F2_STG)               // 122880

template<int MODE>
__global__ __launch_bounds__(256) void gemm_f2(
    const __half* __restrict__ Ah, const __half* __restrict__ Al,
    const __half* __restrict__ Bh, const float* __restrict__ bias,
    float* __restrict__ C, __half* __restrict__ VT,
    int M, int N, int K)
{
    extern __shared__ __align__(1024) char sm[];
    const uint32_t sb = smem_u32(sm);
    const int tid = threadIdx.x;
    const int lane = tid & 31, wid = tid >> 5;
    const int warp_m = wid >> 2, warp_n = wid & 3;
    const int bm = blockIdx.y * 128, bn = blockIdx.x * 256;

    const int lrw = tid >> 1;
    const int lck = (tid & 1) * 2;
    const __half* gAh = Ah + (size_t)(bm + lrw) * K + lck * 8;
    const __half* gAl = Al + (size_t)(bm + lrw) * K + lck * 8;
    const __half* gBh0 = Bh + (size_t)(bn + lrw) * K + lck * 8;
    const __half* gBh1 = gBh0 + (size_t)128 * K;
    const uint32_t dA  = lrw * ROWB + lck * 16;
    const uint32_t dB0 = 2 * A_MATB + lrw * ROWB + lck * 16;
    const uint32_t dB1 = dB0 + 128 * ROWB;

    const int NKT = K / 32;

#define ISSUE(s, kt) do {                                                   \
        const uint32_t so = sb + (s) * F2_STG;                              \
        const size_t go = (size_t)(kt) * 32;                                \
        cp16(so + dA,               gAh + go);                              \
        cp16(so + dA + 16,          gAh + go + 8);                          \
        cp16(so + dA + A_MATB,      gAl + go);                              \
        cp16(so + dA + A_MATB + 16, gAl + go + 8);                          \
        cp16(so + dB0,              gBh0 + go);                             \
        cp16(so + dB0 + 16,         gBh0 + go + 8);                         \
        cp16(so + dB1,              gBh1 + go);                             \
        cp16(so + dB1 + 16,         gBh1 + go + 8);                         \
        CP_COMMIT();                                                       \
    } while (0)

    ISSUE(0, 0);
    ISSUE(1, 1);

    float c[4][8][4];
#pragma unroll
    for (int i = 0; i < 4; i++)
#pragma unroll
        for (int j = 0; j < 8; j++)
#pragma unroll
            for (int q = 0; q < 4; q++) c[i][j][q] = 0.f;

    const uint32_t frow = lane & 15;
    const uint32_t fkb  = ((lane >> 4) & 1) * 16;
    const uint32_t aBase = (warp_m * 64 + frow) * ROWB + fkb;
    const uint32_t bBase = 2 * A_MATB + (warp_n * 64 + frow) * ROWB + fkb;

#pragma unroll 1
    for (int kt = 0; kt < NKT; kt++) {
        if (kt + 1 < NKT) { CP_WAIT(1); } else { CP_WAIT(0); }
        __syncthreads();
        if (kt + 2 < NKT) ISSUE((kt + 2) % 3, kt + 2);
        const uint32_t st = sb + (kt % 3) * F2_STG;

#pragma unroll
        for (int ks = 0; ks < 2; ks++) {
            const uint32_t ko = ks * 32;
            uint32_t ah[4][4], al_[4][4];
#pragma unroll
            for (int mi = 0; mi < 4; mi++) {
                ldsm4(ah[mi],  st + aBase + mi * 16 * ROWB + ko);
                ldsm4(al_[mi], st + A_MATB + aBase + mi * 16 * ROWB + ko);
            }
#pragma unroll
            for (int nb = 0; nb < 4; nb++) {
                uint32_t bh[4];
                ldsm4(bh, st + bBase + nb * 16 * ROWB + ko);
#pragma unroll
                for (int mi = 0; mi < 4; mi++) {
                    mma_h(c[mi][nb * 2],     ah[mi],  bh[0], bh[2]);
                    mma_h(c[mi][nb * 2],     al_[mi], bh[0], bh[2]);
                    mma_h(c[mi][nb * 2 + 1], ah[mi],  bh[1], bh[3]);
                    mma_h(c[mi][nb * 2 + 1], al_[mi], bh[1], bh[3]);
                }
            }
        }
    }

    const int erow = lane >> 2, ecol = (lane & 3) * 2;
#pragma unroll
    for (int mi = 0; mi < 4; mi++) {
        const int r0 = bm + warp_m * 64 + mi * 16 + erow;
#pragma unroll
        for (int n8 = 0; n8 < 8; n8++) {
            const int cc = bn + warp_n * 64 + n8 * 8 + ecol;
            const float b0 = bias[cc], b1 = bias[cc + 1];
            if (MODE == 0) {
                float2 v0 = {c[mi][n8][0] + b0, c[mi][n8][1] + b1};
                float2 v1 = {c[mi][n8][2] + b0, c[mi][n8][3] + b1};
                *(float2*)(C + (size_t)r0 * N + cc)       = v0;
                *(float2*)(C + (size_t)(r0 + 8) * N + cc) = v1;
            } else {
                // V^T: row r = b*NKV + key, col cc = embed -> [b][h][d][key]
#pragma unroll
                for (int rr = 0; rr < 2; rr++) {
                    const int r = r0 + rr * 8;
                    const int bb = r >> 11, key = r & (NKV - 1);
                    const float v0 = c[mi][n8][rr * 2]     + b0;
                    const float v1 = c[mi][n8][rr * 2 + 1] + b1;
                    const size_t o0 = ((size_t)((bb * NH + (cc >> 6)) * HD + (cc & 63))) * NKV + key;
                    const size_t o1 = ((size_t)((bb * NH + ((cc + 1) >> 6)) * HD + ((cc + 1) & 63))) * NKV + key;
                    VT[o0] = __float2half_rn(v0);
                    VT[o1] = __float2half_rn(v1);
                }
            }
        }
    }
#undef ISSUE
}

// ---------------------------------------------------------------------------
// HMMA flash attention: QK^T bf16 3-term, PV fp16 2-term, 3 stages
// ---------------------------------------------------------------------------
#define QROW 144
#define SQ_L   (128 * QROW)
#define SQ_SZ  (2 * 128 * QROW)           // 36864
#define SK_L   (64 * QROW)                // 9216
#define SV     (2 * 64 * QROW)            // 18432
#define SLB    (3 * 64 * QROW)            // 27648
#define STG_SZ (3 * 64 * QROW + 256)      // 27904
#define ASMEM  (SQ_SZ + 3 * STG_SZ)       // 120576

__global__ __launch_bounds__(256) void attn_hmma(
    const __nv_bfloat16* __restrict__ Qh, const __nv_bfloat16* __restrict__ Ql,
    const __nv_bfloat16* __restrict__ Kh, const __nv_bfloat16* __restrict__ Kl,
    const __half* __restrict__ VT, const float* __restrict__ lbG,
    __half* __restrict__ Oh, __half* __restrict__ Ol)
{
    extern __shared__ __align__(1024) char sm[];
    const uint32_t sb = smem_u32(sm);
    const int qt = blockIdx.x, h = blockIdx.y, b = blockIdx.z;
    const int tid = threadIdx.x;
    const int lane = tid & 31, wid = tid >> 5;

    // Q tile via cp.async (pre-scaled, pre-split)
    {
        const int row = tid >> 1;
        const int co = (tid & 1) * 32;
        const __nv_bfloat16* gqh = Qh + ((size_t)(b * NQV + qt * 128 + row)) * EMBED + h * HD + co;
        const __nv_bfloat16* gql = Ql + ((size_t)(b * NQV + qt * 128 + row)) * EMBED + h * HD + co;
        const uint32_t dh = sb + row * QROW + co * 2;
        const uint32_t dl = sb + SQ_L + row * QROW + co * 2;
#pragma unroll
        for (int i = 0; i < 4; i++) {
            cp16(dh + i * 16, gqh + i * 8);
            cp16(dl + i * 16, gql + i * 8);
        }
    }

    const int srow = tid >> 2, scq = tid & 3;
    const __nv_bfloat16* gK_h = Kh + ((size_t)(b * NKV + srow)) * EMBED + h * HD + scq * 16;
    const __nv_bfloat16* gK_l = Kl + ((size_t)(b * NKV + srow)) * EMBED + h * HD + scq * 16;
    const __half* gV = VT + ((size_t)((b * NH + h) * HD + srow)) * NKV + scq * 16;
    const uint32_t sdst = srow * QROW + scq * 32;
    const float* gLB = lbG + (size_t)b * NKV;

#define AISSUE(s, kt) do {                                                  \
        const uint32_t so = sb + SQ_SZ + (s) * STG_SZ;                      \
        const size_t koK = (size_t)(kt) * 64 * EMBED;                       \
        const size_t koV = (size_t)(kt) * 64;                               \
        cp16(so + sdst,             gK_h + koK);                            \
        cp16(so + sdst + 16,        gK_h + koK + 8);                        \
        cp16(so + SK_L + sdst,      gK_l + koK);                            \
        cp16(so + SK_L + sdst + 16, gK_l + koK + 8);                        \
        cp16(so + SV + sdst,        gV + koV);                              \
        cp16(so + SV + sdst + 16,   gV + koV + 8);                          \
        if (tid < 16) cp16(so + SLB + tid * 16, gLB + (kt) * 64 + tid * 4); \
        CP_COMMIT();                                                       \
    } while (0)

    AISSUE(0, 0);   // Q joins group 0
    AISSUE(1, 1);

    const uint32_t frow = lane & 15;
    const uint32_t fkb  = ((lane >> 4) & 1) * 16;
    const uint32_t qBase = (wid * 16 + frow) * QROW + fkb;
    uint32_t qh[4][4];

    float o[8][4];
#pragma unroll
    for (int j = 0; j < 8; j++)
#pragma unroll
        for (int q = 0; q < 4; q++) o[j][q] = 0.f;
    float m0 = -1e30f, m1 = -1e30f, l0 = 0.f, l1 = 0.f;

    const int NT = NKV / 64;
#pragma unroll 1
    for (int kt = 0; kt < NT; kt++) {
        if (kt + 1 < NT) { CP_WAIT(1); } else { CP_WAIT(0); }
        __syncthreads();
        if (kt == 0) {
#pragma unroll
            for (int ks = 0; ks < 4; ks++) ldsm4(qh[ks], sb + qBase + ks * 32);
        }
        if (kt + 2 < NT) AISSUE((kt + 2) % 3, kt + 2);
        const uint32_t st = sb + SQ_SZ + (kt % 3) * STG_SZ;

        // S = Q K^T (bf16 3-term)
        float c[8][4];
#pragma unroll
        for (int j = 0; j < 8; j++)
#pragma unroll
            for (int q = 0; q < 4; q++) c[j][q] = 0.f;

#pragma unroll
        for (int ks = 0; ks < 4; ks++) {
            uint32_t ql_[4];
            ldsm4(ql_, sb + SQ_L + qBase + ks * 32);
#pragma unroll
            for (int nb = 0; nb < 4; nb++) {
                uint32_t kh[4], kl[4];
                const uint32_t ka = st + (nb * 16 + frow) * QROW + fkb + ks * 32;
                ldsm4(kh, ka);
                ldsm4(kl, ka + SK_L);
                mma_bf(c[nb * 2], qh[ks], kh[0], kh[2]);
                mma_bf(c[nb * 2], qh[ks], kl[0], kl[2]);
                mma_bf(c[nb * 2], ql_,    kh[0], kh[2]);
                mma_bf(c[nb * 2 + 1], qh[ks], kh[1], kh[3]);
                mma_bf(c[nb * 2 + 1], qh[ks], kl[1], kl[3]);
                mma_bf(c[nb * 2 + 1], ql_,    kh[1], kh[3]);
            }
        }

        // + log multiplicity
        const float* lbs = (const float*)(sm + SQ_SZ + (kt % 3) * STG_SZ + SLB);
#pragma unroll
        for (int j = 0; j < 8; j++) {
            float2 lb2 = *(const float2*)(lbs + j * 8 + (lane & 3) * 2);
            c[j][0] += lb2.x; c[j][1] += lb2.y;
            c[j][2] += lb2.x; c[j][3] += lb2.y;
        }

        // online softmax
        float rm0 = -1e30f, rm1 = -1e30f;
#pragma unroll
        for (int j = 0; j < 8; j++) {
            rm0 = fmaxf(rm0, fmaxf(c[j][0], c[j][1]));
            rm1 = fmaxf(rm1, fmaxf(c[j][2], c[j][3]));
        }
#pragma unroll
        for (int off = 1; off < 4; off <<= 1) {
            rm0 = fmaxf(rm0, __shfl_xor_sync(0xffffffffu, rm0, off));
            rm1 = fmaxf(rm1, __shfl_xor_sync(0xffffffffu, rm1, off));
        }
        const float mn0 = fmaxf(m0, rm0), mn1 = fmaxf(m1, rm1);
        const float al0 = __expf(m0 - mn0), al1 = __expf(m1 - mn1);
        float rs0 = 0.f, rs1 = 0.f;
#pragma unroll
        for (int j = 0; j < 8; j++) {
            c[j][0] = __expf(c[j][0] - mn0); rs0 += c[j][0];
            c[j][1] = __expf(c[j][1] - mn0); rs0 += c[j][1];
            c[j][2] = __expf(c[j][2] - mn1); rs1 += c[j][2];
            c[j][3] = __expf(c[j][3] - mn1); rs1 += c[j][3];
        }
#pragma unroll
        for (int off = 1; off < 4; off <<= 1) {
            rs0 += __shfl_xor_sync(0xffffffffu, rs0, off);
            rs1 += __shfl_xor_sync(0xffffffffu, rs1, off);
        }
        l0 = l0 * al0 + rs0;  m0 = mn0;
        l1 = l1 * al1 + rs1;  m1 = mn1;
#pragma unroll
        for (int j = 0; j < 8; j++) {
            o[j][0] *= al0; o[j][1] *= al0;
            o[j][2] *= al1; o[j][3] *= al1;
        }

        // O += P V (P fp16 split, V fp16)
#pragma unroll
        for (int kk = 0; kk < 4; kk++) {
            const int j0 = 2 * kk, j1 = 2 * kk + 1;
            float ph[8], pl[8];
            const float pv[8] = {c[j0][0], c[j0][1], c[j0][2], c[j0][3],
                                 c[j1][0], c[j1][1], c[j1][2], c[j1][3]};
#pragma unroll
            for (int q = 0; q < 8; q++) {
                ph[q] = __half2float(__float2half_rn(pv[q]));
                pl[q] = pv[q] - ph[q];
            }
            uint32_t ah[4], al_[4];
            ah[0] = packh(ph[0], ph[1]);  ah[1] = packh(ph[2], ph[3]);
            ah[2] = packh(ph[4], ph[5]);  ah[3] = packh(ph[6], ph[7]);
            al_[0] = packh(pl[0], pl[1]); al_[1] = packh(pl[2], pl[3]);
            al_[2] = packh(pl[4], pl[5]); al_[3] = packh(pl[6], pl[7]);
#pragma unroll
            for (int nb = 0; nb < 4; nb++) {
                uint32_t vh[4];
                ldsm4(vh, st + SV + (nb * 16 + frow) * QROW + fkb + kk * 32);
                mma_h(o[nb * 2], ah,  vh[0], vh[2]);
                mma_h(o[nb * 2], al_, vh[0], vh[2]);
                mma_h(o[nb * 2 + 1], ah,  vh[1], vh[3]);
                mma_h(o[nb * 2 + 1], al_, vh[1], vh[3]);
            }
        }
    }

    // epilogue: normalize, write fp16 hi/lo
    const float inv0 = 1.f / l0, inv1 = 1.f / l1;
    const int r0 = qt * 128 + wid * 16 + (lane >> 2);
    const int cc0 = h * HD + (lane & 3) * 2;
#pragma unroll
    for (int j = 0; j < 8; j++) {
        const int col = cc0 + j * 8;
        {
            float v0 = o[j][0] * inv0, v1 = o[j][1] * inv0;
            float h0 = __half2float(__float2half_rn(v0));
            float h1 = __half2float(__float2half_rn(v1));
            size_t idx = ((size_t)(b * NQV + r0)) * EMBED + col;
            *(uint32_t*)(Oh + idx) = packh(h0, h1);
            *(uint32_t*)(Ol + idx) = packh(v0 - h0, v1 - h1);
        }
        {
            float v0 = o[j][2] * inv1, v1 = o[j][3] * inv1;
            float h0 = __half2float(__float2half_rn(v0));
            float h1 = __half2float(__float2half_rn(v1));
            size_t idx = ((size_t)(b * NQV + r0 + 8)) * EMBED + col;
            *(uint32_t*)(Oh + idx) = packh(h0, h1);
            *(uint32_t*)(Ol + idx) = packh(v0 - h0, v1 - h1);
        }
    }
#undef AISSUE
}

// ---------------------------------------------------------------------------
extern "C" void kernel_launch(void* const* d_in, const int* in_sizes, int n_in,
                              void* d_out, int out_size)
{
    const float* query = (const float*)d_in[0];
    const float* key   = (const float*)d_in[1];
    const float* value = (const float*)d_in[2];
    const float* mult  = (const float*)d_in[3];
    const float* wq_w  = (const float*)d_in[4];
    const float* wq_b  = (const float*)d_in[5];
    const float* wk_w  = (const float*)d_in[6];
    const float* wk_b  = (const float*)d_in[7];
    const float* wv_w  = (const float*)d_in[8];
    const float* wv_b  = (const float*)d_in[9];
    const float* wo_w  = (const float*)d_in[10];
    const float* wo_b  = (const float*)d_in[11];
    float* out = (float*)d_out;

    float* glb;  cudaGetSymbolAddress((void**)&glb, g_lb);
    __nv_bfloat16 *qh,*ql,*kh,*kl,*qsh,*qsl,*ksh,*ksl,*wqh,*wql,*wkh,*wkl;
    __half *vh16,*vl16,*wvh16,*woh16,*vth16,*aoh16,*aol16;
    cudaGetSymbolAddress((void**)&qh, g_qh);   cudaGetSymbolAddress((void**)&ql, g_ql);
    cudaGetSymbolAddress((void**)&kh, g_kh);   cudaGetSymbolAddress((void**)&kl, g_kl);
    cudaGetSymbolAddress((void**)&qsh, g_qsh); cudaGetSymbolAddress((void**)&qsl, g_qsl);
    cudaGetSymbolAddress((void**)&ksh, g_ksh); cudaGetSymbolAddress((void**)&ksl, g_ksl);
    cudaGetSymbolAddress((void**)&wqh, g_wqh); cudaGetSymbolAddress((void**)&wql, g_wql);
    cudaGetSymbolAddress((void**)&wkh, g_wkh); cudaGetSymbolAddress((void**)&wkl, g_wkl);
    cudaGetSymbolAddress((void**)&vh16, g_vh16); cudaGetSymbolAddress((void**)&vl16, g_vl16);
    cudaGetSymbolAddress((void**)&wvh16, g_wvh16);
    cudaGetSymbolAddress((void**)&woh16, g_woh16);
    cudaGetSymbolAddress((void**)&vth16, g_vth16);
    cudaGetSymbolAddress((void**)&aoh16, g_aoh16);
    cudaGetSymbolAddress((void**)&aol16, g_aol16);

    cudaFuncSetAttribute(gemm_bf3<1>, cudaFuncAttributeMaxDynamicSharedMemorySize, GSMEM3);
    cudaFuncSetAttribute(gemm_bf3<2>, cudaFuncAttributeMaxDynamicSharedMemorySize, GSMEM3);
    cudaFuncSetAttribute(gemm_f2<0>, cudaFuncAttributeMaxDynamicSharedMemorySize, F2_SMEM);
    cudaFuncSetAttribute(gemm_f2<3>, cudaFuncAttributeMaxDynamicSharedMemorySize, F2_SMEM);
    cudaFuncSetAttribute(attn_hmma, cudaFuncAttributeMaxDynamicSharedMemorySize, ASMEM);

    const int MQ = BATCH * NQV;
    const int MK = BATCH * NKV;
    const int NW = EMBED * EMBED;

    // launches ordered so ncu (-s 5 -c 1) captures gemm_bf3 (Q projection)
    cvt_split<<<MQ * EMBED / 1024, 256>>>(query, qh, ql);          // 0
    cvt_split<<<NW / 1024, 256>>>(wq_w, wqh, wql);                 // 1
    cvt_split<<<MK * EMBED / 1024, 256>>>(key, kh, kl);            // 2
    cvt_split<<<NW / 1024, 256>>>(wk_w, wkh, wkl);                 // 3
    log_mult<<<MK / 256, 256>>>(mult, glb);                        // 4
    gemm_bf3<2><<<dim3(EMBED / 256, MQ / 128), 256, GSMEM3>>>(     // 5 <- ncu
        qh, ql, wqh, wql, wq_b, qsh, qsl, MQ, EMBED, EMBED);
    gemm_bf3<1><<<dim3(EMBED / 256, MK / 128), 256, GSMEM3>>>(     // 6
        kh, kl, wkh, wkl, wk_b, ksh, ksl, MK, EMBED, EMBED);
    cvt_split_h<<<MK * EMBED / 1024, 256>>>(value, vh16, vl16);    // 7
    cvt_h<<<NW / 1024, 256>>>(wv_w, wvh16);                        // 8
    gemm_f2<3><<<dim3(EMBED / 256, MK / 128), 256, F2_SMEM>>>(     // 9
        vh16, vl16, wvh16, wv_b, nullptr, vth16, MK, EMBED, EMBED);
    attn_hmma<<<dim3(NQV / 128, NH, BATCH), 256, ASMEM>>>(         // 10
        qsh, qsl, ksh, ksl, vth16, glb, aoh16, aol16);
    cvt_h<<<NW / 1024, 256>>>(wo_w, woh16);                        // 11
    gemm_f2<0><<<dim3(EMBED / 256, MQ / 128), 256, F2_SMEM>>>(     // 12
        aoh16, aol16, woh16, wo_b, out, nullptr, MQ, EMBED, EMBED);
}

// round 11
// speedup vs baseline: 3.7632x; 1.3050x over previous
#include <cuda_runtime.h>
#include <cuda_fp16.h>
#include <math.h>
#include <stdint.h>

#define EMBED 1024
#define NQV   1024
#define NKV   2048
#define BATCH 4
#define NH    16
#define HD    64

// ---------------------------------------------------------------------------
// Scratch (__device__ globals — allocation-free rule)
// ---------------------------------------------------------------------------
__device__ float g_lb[BATCH * NKV];

// input fp16 hi/lo splits
__device__ __half g_q16h[BATCH * NQV * EMBED], g_q16l[BATCH * NQV * EMBED];
__device__ __half g_k16h[BATCH * NKV * EMBED], g_k16l[BATCH * NKV * EMBED];
__device__ __half g_v16h[BATCH * NKV * EMBED], g_v16l[BATCH * NKV * EMBED];
// fp16 weights
__device__ __half g_wq16[EMBED * EMBED], g_wk16[EMBED * EMBED];
__device__ __half g_wv16[EMBED * EMBED], g_wo16[EMBED * EMBED];
// projected activations
__device__ __half g_qs16h[BATCH * NQV * EMBED], g_qs16l[BATCH * NQV * EMBED];
__device__ __half g_ks16[BATCH * NKV * EMBED];
__device__ __half g_vt16[BATCH * NH * HD * NKV];
__device__ __half g_ao16h[BATCH * NQV * EMBED], g_ao16l[BATCH * NQV * EMBED];

// ---------------------------------------------------------------------------
// PTX helpers (sm_80-compatible ISA: compute_103 has no 'a' features)
// ---------------------------------------------------------------------------
__device__ __forceinline__ uint32_t smem_u32(const void* p) {
    uint32_t a;
    asm("{ .reg .u64 t; cvta.to.shared.u64 t, %1; cvt.u32.u64 %0, t; }"
        : "=r"(a) : "l"(p));
    return a;
}
__device__ __forceinline__ void cp16(uint32_t dst, const void* src) {
    asm volatile("cp.async.cg.shared.global [%0], [%1], 16;"
                 :: "r"(dst), "l"(src) : "memory");
}
#define CP_COMMIT() asm volatile("cp.async.commit_group;" ::: "memory")
#define CP_WAIT(n)  asm volatile("cp.async.wait_group %0;" :: "n"(n) : "memory")

__device__ __forceinline__ void ldsm4(uint32_t* r, uint32_t addr) {
    asm volatile("ldmatrix.sync.aligned.m8n8.x4.shared.b16 {%0,%1,%2,%3}, [%4];"
                 : "=r"(r[0]), "=r"(r[1]), "=r"(r[2]), "=r"(r[3]) : "r"(addr));
}
__device__ __forceinline__ void mma_h(float* c, const uint32_t* a,
                                      uint32_t b0, uint32_t b1) {
    asm volatile(
        "mma.sync.aligned.m16n8k16.row.col.f32.f16.f16.f32 "
        "{%0,%1,%2,%3}, {%4,%5,%6,%7}, {%8,%9}, {%0,%1,%2,%3};"
        : "+f"(c[0]), "+f"(c[1]), "+f"(c[2]), "+f"(c[3])
        : "r"(a[0]), "r"(a[1]), "r"(a[2]), "r"(a[3]), "r"(b0), "r"(b1));
}
__device__ __forceinline__ uint32_t packh(float lo, float hi) {
    __half2 v = __floats2half2_rn(lo, hi);
    return *(uint32_t*)&v;
}

// ---------------------------------------------------------------------------
// merged conversions
// ---------------------------------------------------------------------------
// q (1M float4 groups) | k (2M) | v (2M) -> fp16 hi/lo
__global__ __launch_bounds__(256) void cvt_inputs(
    const float* __restrict__ q, const float* __restrict__ k,
    const float* __restrict__ v,
    __half* __restrict__ qh, __half* __restrict__ ql,
    __half* __restrict__ kh, __half* __restrict__ kl,
    __half* __restrict__ vh, __half* __restrict__ vl)
{
    const int gid = blockIdx.x * 256 + threadIdx.x;
    const float* src;  __half *dh, *dl;  int idx;
    if (gid < (1 << 20)) {
        src = q; dh = qh; dl = ql; idx = gid * 4;
    } else if (gid < (3 << 20)) {
        src = k; dh = kh; dl = kl; idx = (gid - (1 << 20)) * 4;
    } else {
        src = v; dh = vh; dl = vl; idx = (gid - (3 << 20)) * 4;
    }
    float4 x = *(const float4*)(src + idx);
    __half h0 = __float2half_rn(x.x), h1 = __float2half_rn(x.y);
    __half h2 = __float2half_rn(x.z), h3 = __float2half_rn(x.w);
    *(__half2*)(dh + idx)     = __half2(h0, h1);
    *(__half2*)(dh + idx + 2) = __half2(h2, h3);
    *(__half2*)(dl + idx) = __half2(__float2half_rn(x.x - __half2float(h0)),
                                    __float2half_rn(x.y - __half2float(h1)));
    *(__half2*)(dl + idx + 2) = __half2(__float2half_rn(x.z - __half2float(h2)),
                                        __float2half_rn(x.w - __half2float(h3)));
}

// 4 weight matrices -> single fp16 (262144 float4 groups each)
__global__ __launch_bounds__(256) void cvt_weights(
    const float* __restrict__ w0, const float* __restrict__ w1,
    const float* __restrict__ w2, const float* __restrict__ w3,
    __half* __restrict__ o0, __half* __restrict__ o1,
    __half* __restrict__ o2, __half* __restrict__ o3)
{
    const int gid = blockIdx.x * 256 + threadIdx.x;
    const int seg = gid >> 18;
    const int idx = (gid & 262143) * 4;
    const float* src = (seg == 0) ? w0 : (seg == 1) ? w1 : (seg == 2) ? w2 : w3;
    __half* dst = (seg == 0) ? o0 : (seg == 1) ? o1 : (seg == 2) ? o2 : o3;
    float4 x = *(const float4*)(src + idx);
    *(__half2*)(dst + idx)     = __floats2half2_rn(x.x, x.y);
    *(__half2*)(dst + idx + 2) = __floats2half2_rn(x.z, x.w);
}

__global__ __launch_bounds__(256) void log_mult(const float* __restrict__ m,
                                                float* __restrict__ lb) {
    int i = blockIdx.x * 256 + threadIdx.x;
    lb[i] = __logf(m[i]);
}

// ---------------------------------------------------------------------------
// fp16 2-term HMMA GEMM: C = (Ah+Al) B^T + bias
// Block 128x256, 8 warps 64x64, k-tile 32, 3 stages.
// MODE 0: fp32 out; MODE 3: transposed fp16 V^T [b][h][d][key];
// MODE 4: fp16 hi/lo out, scaled 0.125; MODE 5: fp16 single out
// ---------------------------------------------------------------------------
#define ROWB   80
#define A_MATB (128 * ROWB)
#define B_MATB (256 * ROWB)
#define F2_STG  (2 * A_MATB + B_MATB)      // 40960
#define F2_SMEM (3 * F2_STG)               // 122880

template<int MODE>
__global__ __launch_bounds__(256) void gemm_f2(
    const __half* __restrict__ Ah, const __half* __restrict__ Al,
    const __half* __restrict__ Bh, const float* __restrict__ bias,
    float* __restrict__ C, __half* __restrict__ VT,
    __half* __restrict__ Oh, __half* __restrict__ Ol,
    int M, int N, int K)
{
    extern __shared__ __align__(1024) char sm[];
    const uint32_t sb = smem_u32(sm);
    const int tid = threadIdx.x;
    const int lane = tid & 31, wid = tid >> 5;
    const int warp_m = wid >> 2, warp_n = wid & 3;
    const int bm = blockIdx.y * 128, bn = blockIdx.x * 256;

    const int lrw = tid >> 1;
    const int lck = (tid & 1) * 2;
    const __half* gAh = Ah + (size_t)(bm + lrw) * K + lck * 8;
    const __half* gAl = Al + (size_t)(bm + lrw) * K + lck * 8;
    const __half* gBh0 = Bh + (size_t)(bn + lrw) * K + lck * 8;
    const __half* gBh1 = gBh0 + (size_t)128 * K;
    const uint32_t dA  = lrw * ROWB + lck * 16;
    const uint32_t dB0 = 2 * A_MATB + lrw * ROWB + lck * 16;
    const uint32_t dB1 = dB0 + 128 * ROWB;

    const int NKT = K / 32;

#define ISSUE(s, kt) do {                                                   \
        const uint32_t so = sb + (s) * F2_STG;                              \
        const size_t go = (size_t)(kt) * 32;                                \
        cp16(so + dA,               gAh + go);                              \
        cp16(so + dA + 16,          gAh + go + 8);                          \
        cp16(so + dA + A_MATB,      gAl + go);                              \
        cp16(so + dA + A_MATB + 16, gAl + go + 8);                          \
        cp16(so + dB0,              gBh0 + go);                             \
        cp16(so + dB0 + 16,         gBh0 + go + 8);                         \
        cp16(so + dB1,              gBh1 + go);                             \
        cp16(so + dB1 + 16,         gBh1 + go + 8);                         \
        CP_COMMIT();                                                       \
    } while (0)

    ISSUE(0, 0);
    ISSUE(1, 1);

    float c[4][8][4];
#pragma unroll
    for (int i = 0; i < 4; i++)
#pragma unroll
        for (int j = 0; j < 8; j++)
#pragma unroll
            for (int q = 0; q < 4; q++) c[i][j][q] = 0.f;

    const uint32_t frow = lane & 15;
    const uint32_t fkb  = ((lane >> 4) & 1) * 16;
    const uint32_t aBase = (warp_m * 64 + frow) * ROWB + fkb;
    const uint32_t bBase = 2 * A_MATB + (warp_n * 64 + frow) * ROWB + fkb;

#pragma unroll 1
    for (int kt = 0; kt < NKT; kt++) {
        if (kt + 1 < NKT) { CP_WAIT(1); } else { CP_WAIT(0); }
        __syncthreads();
        if (kt + 2 < NKT) ISSUE((kt + 2) % 3, kt + 2);
        const uint32_t st = sb + (kt % 3) * F2_STG;

#pragma unroll
        for (int ks = 0; ks < 2; ks++) {
            const uint32_t ko = ks * 32;
            uint32_t ah[4][4], al_[4][4];
#pragma unroll
            for (int mi = 0; mi < 4; mi++) {
                ldsm4(ah[mi],  st + aBase + mi * 16 * ROWB + ko);
                ldsm4(al_[mi], st + A_MATB + aBase + mi * 16 * ROWB + ko);
            }
#pragma unroll
            for (int nb = 0; nb < 4; nb++) {
                uint32_t bh[4];
                ldsm4(bh, st + bBase + nb * 16 * ROWB + ko);
#pragma unroll
                for (int mi = 0; mi < 4; mi++) {
                    mma_h(c[mi][nb * 2],     ah[mi],  bh[0], bh[2]);
                    mma_h(c[mi][nb * 2],     al_[mi], bh[0], bh[2]);
                    mma_h(c[mi][nb * 2 + 1], ah[mi],  bh[1], bh[3]);
                    mma_h(c[mi][nb * 2 + 1], al_[mi], bh[1], bh[3]);
                }
            }
        }
    }

    const int erow = lane >> 2, ecol = (lane & 3) * 2;
#pragma unroll
    for (int mi = 0; mi < 4; mi++) {
        const int r0 = bm + warp_m * 64 + mi * 16 + erow;
#pragma unroll
        for (int n8 = 0; n8 < 8; n8++) {
            const int cc = bn + warp_n * 64 + n8 * 8 + ecol;
            const float b0 = bias[cc], b1 = bias[cc + 1];
            if (MODE == 0) {
                float2 v0 = {c[mi][n8][0] + b0, c[mi][n8][1] + b1};
                float2 v1 = {c[mi][n8][2] + b0, c[mi][n8][3] + b1};
                *(float2*)(C + (size_t)r0 * N + cc)       = v0;
                *(float2*)(C + (size_t)(r0 + 8) * N + cc) = v1;
            } else if (MODE == 3) {
#pragma unroll
                for (int rr = 0; rr < 2; rr++) {
                    const int r = r0 + rr * 8;
                    const int bb = r >> 11, key = r & (NKV - 1);
                    const float v0 = c[mi][n8][rr * 2]     + b0;
                    const float v1 = c[mi][n8][rr * 2 + 1] + b1;
                    const size_t o0 = ((size_t)((bb * NH + (cc >> 6)) * HD + (cc & 63))) * NKV + key;
                    const size_t o1 = ((size_t)((bb * NH + ((cc + 1) >> 6)) * HD + ((cc + 1) & 63))) * NKV + key;
                    VT[o0] = __float2half_rn(v0);
                    VT[o1] = __float2half_rn(v1);
                }
            } else if (MODE == 4) {
                float x0 = (c[mi][n8][0] + b0) * 0.125f, x1 = (c[mi][n8][1] + b1) * 0.125f;
                float x2 = (c[mi][n8][2] + b0) * 0.125f, x3 = (c[mi][n8][3] + b1) * 0.125f;
                float h0 = __half2float(__float2half_rn(x0));
                float h1 = __half2float(__float2half_rn(x1));
                float h2 = __half2float(__float2half_rn(x2));
                float h3 = __half2float(__float2half_rn(x3));
                size_t i0 = (size_t)r0 * N + cc, i1 = (size_t)(r0 + 8) * N + cc;
                *(uint32_t*)(Oh + i0) = packh(h0, h1);
                *(uint32_t*)(Oh + i1) = packh(h2, h3);
                *(uint32_t*)(Ol + i0) = packh(x0 - h0, x1 - h1);
                *(uint32_t*)(Ol + i1) = packh(x2 - h2, x3 - h3);
            } else {  // MODE 5: fp16 single
                size_t i0 = (size_t)r0 * N + cc, i1 = (size_t)(r0 + 8) * N + cc;
                *(uint32_t*)(Oh + i0) = packh(c[mi][n8][0] + b0, c[mi][n8][1] + b1);
                *(uint32_t*)(Oh + i1) = packh(c[mi][n8][2] + b0, c[mi][n8][3] + b1);
            }
        }
    }
#undef ISSUE
}

// ---------------------------------------------------------------------------
// fp16 HMMA flash attention: S = (Qh+Ql)K^T + log m; O = (Ph+Pl)V
// ---------------------------------------------------------------------------
#define QROW 144
#define SQ_L   (128 * QROW)               // 18432
#define SQ_SZ  (2 * 128 * QROW)           // 36864
#define SV     (64 * QROW)                // 9216 (V plane offset in stage)
#define SLB    (2 * 64 * QROW)            // 18432 (lb offset in stage)
#define STG_SZ (2 * 64 * QROW + 256)      // 18688
#define ASMEM  (SQ_SZ + 3 * STG_SZ)       // 92928

__global__ __launch_bounds__(256) void attn_hmma(
    const __half* __restrict__ Qh, const __half* __restrict__ Ql,
    const __half* __restrict__ Kf, const __half* __restrict__ VT,
    const float* __restrict__ lbG,
    __half* __restrict__ Oh, __half* __restrict__ Ol)
{
    extern __shared__ __align__(1024) char sm[];
    const uint32_t sb = smem_u32(sm);
    const int qt = blockIdx.x, h = blockIdx.y, b = blockIdx.z;
    const int tid = threadIdx.x;
    const int lane = tid & 31, wid = tid >> 5;

    // Q tile via cp.async (pre-scaled hi/lo)
    {
        const int row = tid >> 1;
        const int co = (tid & 1) * 32;
        const __half* gqh = Qh + ((size_t)(b * NQV + qt * 128 + row)) * EMBED + h * HD + co;
        const __half* gql = Ql + ((size_t)(b * NQV + qt * 128 + row)) * EMBED + h * HD + co;
        const uint32_t dh = sb + row * QROW + co * 2;
        const uint32_t dl = sb + SQ_L + row * QROW + co * 2;
#pragma unroll
        for (int i = 0; i < 4; i++) {
            cp16(dh + i * 16, gqh + i * 8);
            cp16(dl + i * 16, gql + i * 8);
        }
    }

    const int srow = tid >> 2, scq = tid & 3;
    const __half* gK = Kf + ((size_t)(b * NKV + srow)) * EMBED + h * HD + scq * 16;
    const __half* gV = VT + ((size_t)((b * NH + h) * HD + srow)) * NKV + scq * 16;
    const uint32_t sdst = srow * QROW + scq * 32;
    const float* gLB = lbG + (size_t)b * NKV;

#define AISSUE(s, kt) do {                                                  \
        const uint32_t so = sb + SQ_SZ + (s) * STG_SZ;                      \
        const size_t koK = (size_t)(kt) * 64 * EMBED;                       \
        const size_t koV = (size_t)(kt) * 64;                               \
        cp16(so + sdst,           gK + koK);                                \
        cp16(so + sdst + 16,      gK + koK + 8);                            \
        cp16(so + SV + sdst,      gV + koV);                                \
        cp16(so + SV + sdst + 16, gV + koV + 8);                            \
        if (tid < 16) cp16(so + SLB + tid * 16, gLB + (kt) * 64 + tid * 4); \
        CP_COMMIT();                                                       \
    } while (0)

    AISSUE(0, 0);   // Q joins group 0
    AISSUE(1, 1);

    const uint32_t frow = lane & 15;
    const uint32_t fkb  = ((lane >> 4) & 1) * 16;
    const uint32_t qBase = (wid * 16 + frow) * QROW + fkb;
    uint32_t qhf[4][4];

    float o[8][4];
#pragma unroll
    for (int j = 0; j < 8; j++)
#pragma unroll
        for (int q = 0; q < 4; q++) o[j][q] = 0.f;
    float m0 = -1e30f, m1 = -1e30f, l0 = 0.f, l1 = 0.f;

    const int NT = NKV / 64;
#pragma unroll 1
    for (int kt = 0; kt < NT; kt++) {
        if (kt + 1 < NT) { CP_WAIT(1); } else { CP_WAIT(0); }
        __syncthreads();
        if (kt == 0) {
#pragma unroll
            for (int ks = 0; ks < 4; ks++) ldsm4(qhf[ks], sb + qBase + ks * 32);
        }
        if (kt + 2 < NT) AISSUE((kt + 2) % 3, kt + 2);
        const uint32_t st = sb + SQ_SZ + (kt % 3) * STG_SZ;

        // S = (Qh+Ql) K^T
        float c[8][4];
#pragma unroll
        for (int j = 0; j < 8; j++)
#pragma unroll
            for (int q = 0; q < 4; q++) c[j][q] = 0.f;

#pragma unroll
        for (int ks = 0; ks < 4; ks++) {
            uint32_t ql_[4];
            ldsm4(ql_, sb + SQ_L + qBase + ks * 32);
#pragma unroll
            for (int nb = 0; nb < 4; nb++) {
                uint32_t kf[4];
                ldsm4(kf, st + (nb * 16 + frow) * QROW + fkb + ks * 32);
                mma_h(c[nb * 2], qhf[ks], kf[0], kf[2]);
                mma_h(c[nb * 2], ql_,     kf[0], kf[2]);
                mma_h(c[nb * 2 + 1], qhf[ks], kf[1], kf[3]);
                mma_h(c[nb * 2 + 1], ql_,     kf[1], kf[3]);
            }
        }

        // + log multiplicity
        const float* lbs = (const float*)(sm + SQ_SZ + (kt % 3) * STG_SZ + SLB);
#pragma unroll
        for (int j = 0; j < 8; j++) {
            float2 lb2 = *(const float2*)(lbs + j * 8 + (lane & 3) * 2);
            c[j][0] += lb2.x; c[j][1] += lb2.y;
            c[j][2] += lb2.x; c[j][3] += lb2.y;
        }

        // online softmax
        float rm0 = -1e30f, rm1 = -1e30f;
#pragma unroll
        for (int j = 0; j < 8; j++) {
            rm0 = fmaxf(rm0, fmaxf(c[j][0], c[j][1]));
            rm1 = fmaxf(rm1, fmaxf(c[j][2], c[j][3]));
        }
#pragma unroll
        for (int off = 1; off < 4; off <<= 1) {
            rm0 = fmaxf(rm0, __shfl_xor_sync(0xffffffffu, rm0, off));
            rm1 = fmaxf(rm1, __shfl_xor_sync(0xffffffffu, rm1, off));
        }
        const float mn0 = fmaxf(m0, rm0), mn1 = fmaxf(m1, rm1);
        const float al0 = __expf(m0 - mn0), al1 = __expf(m1 - mn1);
        float rs0 = 0.f, rs1 = 0.f;
#pragma unroll
        for (int j = 0; j < 8; j++) {
            c[j][0] = __expf(c[j][0] - mn0); rs0 += c[j][0];
            c[j][1] = __expf(c[j][1] - mn0); rs0 += c[j][1];
            c[j][2] = __expf(c[j][2] - mn1); rs1 += c[j][2];
            c[j][3] = __expf(c[j][3] - mn1); rs1 += c[j][3];
        }
#pragma unroll
        for (int off = 1; off < 4; off <<= 1) {
            rs0 += __shfl_xor_sync(0xffffffffu, rs0, off);
            rs1 += __shfl_xor_sync(0xffffffffu, rs1, off);
        }
        l0 = l0 * al0 + rs0;  m0 = mn0;
        l1 = l1 * al1 + rs1;  m1 = mn1;
#pragma unroll
        for (int j = 0; j < 8; j++) {
            o[j][0] *= al0; o[j][1] *= al0;
            o[j][2] *= al1; o[j][3] *= al1;
        }

        // O += (Ph+Pl) V
#pragma unroll
        for (int kk = 0; kk < 4; kk++) {
            const int j0 = 2 * kk, j1 = 2 * kk + 1;
            float ph[8], pl[8];
            const float pv[8] = {c[j0][0], c[j0][1], c[j0][2], c[j0][3],
                                 c[j1][0], c[j1][1], c[j1][2], c[j1][3]};
#pragma unroll
            for (int q = 0; q < 8; q++) {
                ph[q] = __half2float(__float2half_rn(pv[q]));
                pl[q] = pv[q] - ph[q];
            }
            uint32_t ah[4], al_[4];
            ah[0] = packh(ph[0], ph[1]);  ah[1] = packh(ph[2], ph[3]);
            ah[2] = packh(ph[4], ph[5]);  ah[3] = packh(ph[6], ph[7]);
            al_[0] = packh(pl[0], pl[1]); al_[1] = packh(pl[2], pl[3]);
            al_[2] = packh(pl[4], pl[5]); al_[3] = packh(pl[6], pl[7]);
#pragma unroll
            for (int nb = 0; nb < 4; nb++) {
                uint32_t vh[4];
                ldsm4(vh, st + SV + (nb * 16 + frow) * QROW + fkb + kk * 32);
                mma_h(o[nb * 2], ah,  vh[0], vh[2]);
                mma_h(o[nb * 2], al_, vh[0], vh[2]);
                mma_h(o[nb * 2 + 1], ah,  vh[1], vh[3]);
                mma_h(o[nb * 2 + 1], al_, vh[1], vh[3]);
            }
        }
    }

    // epilogue: normalize, write fp16 hi/lo
    const float inv0 = 1.f / l0, inv1 = 1.f / l1;
    const int r0 = qt * 128 + wid * 16 + (lane >> 2);
    const int cc0 = h * HD + (lane & 3) * 2;
#pragma unroll
    for (int j = 0; j < 8; j++) {
        const int col = cc0 + j * 8;
        {
            float v0 = o[j][0] * inv0, v1 = o[j][1] * inv0;
            float h0 = __half2float(__float2half_rn(v0));
            float h1 = __half2float(__float2half_rn(v1));
            size_t idx = ((size_t)(b * NQV + r0)) * EMBED + col;
            *(uint32_t*)(Oh + idx) = packh(h0, h1);
            *(uint32_t*)(Ol + idx) = packh(v0 - h0, v1 - h1);
        }
        {
            float v0 = o[j][2] * inv1, v1 = o[j][3] * inv1;
            float h0 = __half2float(__float2half_rn(v0));
            float h1 = __half2float(__float2half_rn(v1));
            size_t idx = ((size_t)(b * NQV + r0 + 8)) * EMBED + col;
            *(uint32_t*)(Oh + idx) = packh(h0, h1);
            *(uint32_t*)(Ol + idx) = packh(v0 - h0, v1 - h1);
        }
    }
#undef AISSUE
}

// ---------------------------------------------------------------------------
extern "C" void kernel_launch(void* const* d_in, const int* in_sizes, int n_in,
                              void* d_out, int out_size)
{
    const float* query = (const float*)d_in[0];
    const float* key   = (const float*)d_in[1];
    const float* value = (const float*)d_in[2];
    const float* mult  = (const float*)d_in[3];
    const float* wq_w  = (const float*)d_in[4];
    const float* wq_b  = (const float*)d_in[5];
    const float* wk_w  = (const float*)d_in[6];
    const float* wk_b  = (const float*)d_in[7];
    const float* wv_w  = (const float*)d_in[8];
    const float* wv_b  = (const float*)d_in[9];
    const float* wo_w  = (const float*)d_in[10];
    const float* wo_b  = (const float*)d_in[11];
    float* out = (float*)d_out;

    float* glb;  cudaGetSymbolAddress((void**)&glb, g_lb);
    __half *q16h,*q16l,*k16h,*k16l,*v16h,*v16l;
    __half *wq16,*wk16,*wv16,*wo16;
    __half *qs16h,*qs16l,*ks16,*vt16,*ao16h,*ao16l;
    cudaGetSymbolAddress((void**)&q16h, g_q16h); cudaGetSymbolAddress((void**)&q16l, g_q16l);
    cudaGetSymbolAddress((void**)&k16h, g_k16h); cudaGetSymbolAddress((void**)&k16l, g_k16l);
    cudaGetSymbolAddress((void**)&v16h, g_v16h); cudaGetSymbolAddress((void**)&v16l, g_v16l);
    cudaGetSymbolAddress((void**)&wq16, g_wq16); cudaGetSymbolAddress((void**)&wk16, g_wk16);
    cudaGetSymbolAddress((void**)&wv16, g_wv16); cudaGetSymbolAddress((void**)&wo16, g_wo16);
    cudaGetSymbolAddress((void**)&qs16h, g_qs16h); cudaGetSymbolAddress((void**)&qs16l, g_qs16l);
    cudaGetSymbolAddress((void**)&ks16, g_ks16);
    cudaGetSymbolAddress((void**)&vt16, g_vt16);
    cudaGetSymbolAddress((void**)&ao16h, g_ao16h); cudaGetSymbolAddress((void**)&ao16l, g_ao16l);

    cudaFuncSetAttribute(gemm_f2<0>, cudaFuncAttributeMaxDynamicSharedMemorySize, F2_SMEM);
    cudaFuncSetAttribute(gemm_f2<3>, cudaFuncAttributeMaxDynamicSharedMemorySize, F2_SMEM);
    cudaFuncSetAttribute(gemm_f2<4>, cudaFuncAttributeMaxDynamicSharedMemorySize, F2_SMEM);
    cudaFuncSetAttribute(gemm_f2<5>, cudaFuncAttributeMaxDynamicSharedMemorySize, F2_SMEM);
    cudaFuncSetAttribute(attn_hmma, cudaFuncAttributeMaxDynamicSharedMemorySize, ASMEM);

    const int MQ = BATCH * NQV;   // 4096
    const int MK = BATCH * NKV;   // 8192

    // 0: inputs -> fp16 hi/lo  (5M float4 groups)
    cvt_inputs<<<20480, 256>>>(query, key, value,
                               q16h, q16l, k16h, k16l, v16h, v16l);
    // 1: weights -> fp16
    cvt_weights<<<4096, 256>>>(wq_w, wk_w, wv_w, wo_w, wq16, wk16, wv16, wo16);
    // 2: log multiplicities
    log_mult<<<MK / 256, 256>>>(mult, glb);
    // 3: Q proj -> scaled fp16 hi/lo
    gemm_f2<4><<<dim3(EMBED / 256, MQ / 128), 256, F2_SMEM>>>(
        q16h, q16l, wq16, wq_b, nullptr, nullptr, qs16h, qs16l, MQ, EMBED, EMBED);
    // 4: K proj -> fp16 single
    gemm_f2<5><<<dim3(EMBED / 256, MK / 128), 256, F2_SMEM>>>(
        k16h, k16l, wk16, wk_b, nullptr, nullptr, ks16, nullptr, MK, EMBED, EMBED);
    // 5 (ncu): V proj -> transposed fp16 V^T
    gemm_f2<3><<<dim3(EMBED / 256, MK / 128), 256, F2_SMEM>>>(
        v16h, v16l, wv16, wv_b, nullptr, vt16, nullptr, nullptr, MK, EMBED, EMBED);
    // 6: attention
    attn_hmma<<<dim3(NQV / 128, NH, BATCH), 256, ASMEM>>>(
        qs16h, qs16l, ks16, vt16, glb, ao16h, ao16l);
    // 7: O proj -> fp32 out
    gemm_f2<0><<<dim3(EMBED / 256, MQ / 128), 256, F2_SMEM>>>(
        ao16h, ao16l, wo16, wo_b, out, nullptr, nullptr, nullptr, MQ, EMBED, EMBED);
}